// round 14
// baseline (speedup 1.0000x reference)
#include <cuda_runtime.h>
#include <cuda_bf16.h>
#include <cstdint>

// Problem constants
#define EMBED 2048
#define NHEAD 16
#define NKV   4
#define HDIM  128
#define BB    2
#define SS    2048
#define MROWS (BB*SS)          // 4096
#define KVDIM (NKV*HDIM)       // 512

typedef __nv_bfloat16 bf16;

// -------- scratch (no allocation allowed) --------
#define IN_STRIDE (MROWS * EMBED)
__device__ bf16 g_inh[3 * IN_STRIDE];
__device__ bf16 g_inl[3 * IN_STRIDE];
#define WQ_OFF 0
#define WK_OFF (EMBED*EMBED)
#define WV_OFF (WK_OFF + EMBED*KVDIM)
#define WO_OFF (WV_OFF + EMBED*KVDIM)
#define W_TOTAL (WO_OFF + EMBED*EMBED)
__device__ bf16 g_wh[W_TOTAL];
__device__ bf16 g_wl[W_TOTAL];
__device__ bf16 g_qh[MROWS * EMBED];
__device__ bf16 g_ql[MROWS * EMBED];
__device__ bf16 g_kh[MROWS * KVDIM];
__device__ bf16 g_kl[MROWS * KVDIM];
__device__ bf16 g_vh[MROWS * KVDIM];
__device__ bf16 g_vl[MROWS * KVDIM];
__device__ bf16 g_ctxh[MROWS * EMBED];
__device__ bf16 g_ctxl[MROWS * EMBED];

// ======================= helpers =======================
__device__ __forceinline__ uint32_t sptr(const void* p) {
    return (uint32_t)__cvta_generic_to_shared(p);
}
__device__ __forceinline__ void cpa16(uint32_t dst, const void* src) {
    asm volatile("cp.async.cg.shared.global [%0], [%1], 16;" :: "r"(dst), "l"(src));
}
#define CP_COMMIT() asm volatile("cp.async.commit_group;")
#define CP_WAIT(n)  asm volatile("cp.async.wait_group %0;" :: "n"(n))

__device__ __forceinline__ void ldsm4(uint32_t& r0, uint32_t& r1, uint32_t& r2, uint32_t& r3, uint32_t a) {
    asm volatile("ldmatrix.sync.aligned.m8n8.x4.shared.b16 {%0,%1,%2,%3},[%4];"
                 : "=r"(r0), "=r"(r1), "=r"(r2), "=r"(r3) : "r"(a));
}
__device__ __forceinline__ void ldsm4t(uint32_t& r0, uint32_t& r1, uint32_t& r2, uint32_t& r3, uint32_t a) {
    asm volatile("ldmatrix.sync.aligned.m8n8.x4.trans.shared.b16 {%0,%1,%2,%3},[%4];"
                 : "=r"(r0), "=r"(r1), "=r"(r2), "=r"(r3) : "r"(a));
}
__device__ __forceinline__ void mma_bf16(float* c, const uint32_t* a, uint32_t b0, uint32_t b1) {
    asm volatile(
        "mma.sync.aligned.m16n8k16.row.col.f32.bf16.bf16.f32 "
        "{%0,%1,%2,%3},{%4,%5,%6,%7},{%8,%9},{%0,%1,%2,%3};"
        : "+f"(c[0]), "+f"(c[1]), "+f"(c[2]), "+f"(c[3])
        : "r"(a[0]), "r"(a[1]), "r"(a[2]), "r"(a[3]), "r"(b0), "r"(b1));
}
__device__ __forceinline__ uint32_t packbf2(float lo, float hi) {
    uint32_t r;
    asm("cvt.rn.bf16x2.f32 %0, %1, %2;" : "=r"(r) : "f"(hi), "f"(lo));
    return r;
}
__device__ __forceinline__ float ex2(float x) {
    float r;
    asm("ex2.approx.ftz.f32 %0, %1;" : "=f"(r) : "f"(x));
    return r;
}
__device__ __forceinline__ void split_store4(float4 v, bf16* ph, bf16* pl) {
    bf16 h0 = __float2bfloat16_rn(v.x), h1 = __float2bfloat16_rn(v.y),
         h2 = __float2bfloat16_rn(v.z), h3 = __float2bfloat16_rn(v.w);
    ((__nv_bfloat162*)ph)[0] = __halves2bfloat162(h0, h1);
    ((__nv_bfloat162*)ph)[1] = __halves2bfloat162(h2, h3);
    ((__nv_bfloat162*)pl)[0] = __floats2bfloat162_rn(v.x - __bfloat162float(h0), v.y - __bfloat162float(h1));
    ((__nv_bfloat162*)pl)[1] = __floats2bfloat162_rn(v.z - __bfloat162float(h2), v.w - __bfloat162float(h3));
}
__device__ __forceinline__ void split_store2(float v0, float v1, bf16* ph, bf16* pl) {
    bf16 h0 = __float2bfloat16_rn(v0), h1 = __float2bfloat16_rn(v1);
    *(__nv_bfloat162*)ph = __halves2bfloat162(h0, h1);
    *(__nv_bfloat162*)pl = __floats2bfloat162_rn(v0 - __bfloat162float(h0), v1 - __bfloat162float(h1));
}

// ============================================================
// fused split: all 7 tensors in one launch
// ============================================================
struct SplitArgs {
    const float* src[7];
    bf16* dh[7];
    bf16* dl[7];
};
#define SPLIT_BLOCKS 34816

__global__ __launch_bounds__(256)
void fused_split(SplitArgs a)
{
    int idx = blockIdx.x * 256 + threadIdx.x;   // float4 index
    int seg, off;
    if (idx < 6291456) {                         // query/key/value
        seg = idx / 2097152; off = idx - seg * 2097152;
    } else if (idx < 7340032) { seg = 3; off = idx - 6291456; }
    else if (idx < 7602176)   { seg = 4; off = idx - 7340032; }
    else if (idx < 7864320)   { seg = 5; off = idx - 7602176; }
    else                      { seg = 6; off = idx - 7864320; }
    float4 v = ((const float4*)a.src[seg])[off];
    split_store4(v, a.dh[seg] + (size_t)off * 4, a.dl[seg] + (size_t)off * 4);
}

// ============================================================
// GEMM tile body
// BM=BN=128, BK=32, 256 threads, 3-stage cp.async, 2 CTAs/SM.
// Single __syncthreads per K-step (issue hoisted behind barrier).
// ============================================================
#define ALD 40
#define BLD 136
#define G_A_ELEMS (128*ALD)
#define G_B_ELEMS (32*BLD)
#define G_STG (2*G_A_ELEMS + 2*G_B_ELEMS)
#define GEMM_SMEM (3 * G_STG * 2)

template<typename EPILOGUE>
__device__ __forceinline__ void gemm_tile(
    const bf16* __restrict__ Ah_g, const bf16* __restrict__ Al_g,
    const bf16* __restrict__ Bh_g, const bf16* __restrict__ Bl_g,
    int N, int K, int bm, int bn, bf16* smg, EPILOGUE epi)
{
    const int tid = threadIdx.x;
    const size_t aBase = (size_t)bm * 128 * K;
    const size_t bBase = (size_t)bn * 128;

    const int w = tid >> 5, lane = tid & 31;
    const int m0w = (w >> 2) * 64, n0w = (w & 3) * 32;
    const int arow = lane & 15, asel = (lane >> 4) * 8;
    const int brow = (lane & 7) + (lane & 8);
    const int bsel = (lane & 16) >> 1;

    float acc[4][4][4];
    #pragma unroll
    for (int mt = 0; mt < 4; mt++)
        #pragma unroll
        for (int nt = 0; nt < 4; nt++)
            #pragma unroll
            for (int i = 0; i < 4; i++) acc[mt][nt][i] = 0.f;

    const int nk = K / 32;

    auto issue = [&](int kt, int s) {
        bf16* sAh = smg + (size_t)s * G_STG;
        bf16* sAl = sAh + G_A_ELEMS;
        bf16* sBh = sAl + G_A_ELEMS;
        bf16* sBl = sBh + G_B_ELEMS;
        const int k0 = kt * 32;
        #pragma unroll
        for (int j = 0; j < 2; j++) {
            int c = tid + 256 * j;
            int r = c >> 2, kc = (c & 3) * 8;
            size_t go = aBase + (size_t)r * K + k0 + kc;
            int so = r * ALD + kc;
            cpa16(sptr(sAh + so), Ah_g + go);
            cpa16(sptr(sAl + so), Al_g + go);
        }
        #pragma unroll
        for (int j = 0; j < 2; j++) {
            int c = tid + 256 * j;
            int r = c >> 4, nc = (c & 15) * 8;
            size_t go = bBase + (size_t)(k0 + r) * N + nc;
            int so = r * BLD + nc;
            cpa16(sptr(sBh + so), Bh_g + go);
            cpa16(sptr(sBl + so), Bl_g + go);
        }
        CP_COMMIT();
    };

    issue(0, 0);
    if (nk > 1) issue(1, 1);

    for (int kt = 0; kt < nk; kt++) {
        const int s = kt % 3;
        if (kt + 1 < nk) { CP_WAIT(1); } else { CP_WAIT(0); }
        __syncthreads();
        // safe: all warps finished compute(kt-1), the only reader of stage (kt+2)%3
        if (kt + 2 < nk) issue(kt + 2, (kt + 2) % 3);

        bf16* sAh = smg + (size_t)s * G_STG;
        bf16* sAl = sAh + G_A_ELEMS;
        bf16* sBh = sAl + G_A_ELEMS;
        bf16* sBl = sBh + G_B_ELEMS;

        #pragma unroll
        for (int kk = 0; kk < 2; kk++) {
            uint32_t ah[4][4], al[4][4];
            #pragma unroll
            for (int mt = 0; mt < 4; mt++) {
                int off = (m0w + 16 * mt + arow) * ALD + 16 * kk + asel;
                ldsm4(ah[mt][0], ah[mt][1], ah[mt][2], ah[mt][3], sptr(&sAh[off]));
                ldsm4(al[mt][0], al[mt][1], al[mt][2], al[mt][3], sptr(&sAl[off]));
            }
            uint32_t bh[4][2], bl[4][2];
            #pragma unroll
            for (int nt2 = 0; nt2 < 2; nt2++) {
                int off = (16 * kk + brow) * BLD + n0w + 16 * nt2 + bsel;
                uint32_t r0, r1, r2, r3;
                ldsm4t(r0, r1, r2, r3, sptr(&sBh[off]));
                bh[2*nt2][0] = r0; bh[2*nt2][1] = r1; bh[2*nt2+1][0] = r2; bh[2*nt2+1][1] = r3;
                ldsm4t(r0, r1, r2, r3, sptr(&sBl[off]));
                bl[2*nt2][0] = r0; bl[2*nt2][1] = r1; bl[2*nt2+1][0] = r2; bl[2*nt2+1][1] = r3;
            }
            #pragma unroll
            for (int mt = 0; mt < 4; mt++)
                #pragma unroll
                for (int nt = 0; nt < 4; nt++) {
                    mma_bf16(acc[mt][nt], ah[mt], bh[nt][0], bh[nt][1]);
                    mma_bf16(acc[mt][nt], ah[mt], bl[nt][0], bl[nt][1]);
                    mma_bf16(acc[mt][nt], al[mt], bh[nt][0], bh[nt][1]);
                }
        }
    }

    const int g = lane >> 2, t = lane & 3;
    #pragma unroll
    for (int mt = 0; mt < 4; mt++)
        #pragma unroll
        for (int nt = 0; nt < 4; nt++) {
            size_t r0 = (size_t)bm * 128 + m0w + 16 * mt + g;
            size_t c0 = (size_t)bn * 128 + n0w + 8 * nt + 2 * t;
            epi(r0, c0, acc[mt][nt][0], acc[mt][nt][1]);
            epi(r0 + 8, c0, acc[mt][nt][2], acc[mt][nt][3]);
        }
}

// ---- fused Q/K/V projection ----
struct ProjArgs {
    const bf16* Ah[3]; const bf16* Al[3];
    const bf16* Bh[3]; const bf16* Bl[3];
    bf16* Ch[3]; bf16* Cl[3];
};

__global__ __launch_bounds__(256, 2)
void gemm_proj(ProjArgs p)
{
    extern __shared__ bf16 smg[];
    int bid = blockIdx.x;
    int gsel, bm, bn, N;
    if (bid < 512) {
        gsel = 0; bm = bid >> 4; bn = bid & 15; N = EMBED;
    } else {
        int u = bid - 512;
        gsel = 1 + (u >> 7);
        u &= 127;
        bm = u >> 2; bn = u & 3; N = KVDIM;
    }
    bf16* Ch = p.Ch[gsel];
    bf16* Cl = p.Cl[gsel];
    gemm_tile(p.Ah[gsel], p.Al[gsel], p.Bh[gsel], p.Bl[gsel], N, EMBED, bm, bn, smg,
        [&](size_t r, size_t c, float v0, float v1) {
            split_store2(v0, v1, &Ch[r * N + c], &Cl[r * N + c]);
        });
}

// ---- O projection: fp32 out ----
__global__ __launch_bounds__(256, 2)
void gemm_out(const bf16* __restrict__ Ah_g, const bf16* __restrict__ Al_g,
              const bf16* __restrict__ Bh_g, const bf16* __restrict__ Bl_g,
              float* __restrict__ Cf)
{
    extern __shared__ bf16 smg[];
    int bm = blockIdx.y, bn = blockIdx.x;
    gemm_tile(Ah_g, Al_g, Bh_g, Bl_g, EMBED, EMBED, bm, bn, smg,
        [&](size_t r, size_t c, float v0, float v1) {
            float2 u; u.x = v0; u.y = v1;
            *(float2*)&Cf[r * EMBED + c] = u;
        });
}

// ============================================================
// Flash attention, bf16-split mma.sync, base-2 softmax.
// 128 threads (4 warps), 64 q-rows/CTA, KV tile 32.
// smem 69.9KB -> 3 CTAs/SM (launch_bounds(128,3), regs<=170).
// Single __syncthreads per KV tile.
// ============================================================
#define KTILE 32
#define KLD 136
#define A_STG (4 * KTILE * KLD)
#define ATTN_SMEM (2 * A_STG * 2 + 2 * KTILE * 4)

__global__ __launch_bounds__(128, 3)
void attn_mma(const bf16* __restrict__ Qh, const bf16* __restrict__ Ql,
              const bf16* __restrict__ Kh, const bf16* __restrict__ Kl,
              const bf16* __restrict__ Vh, const bf16* __restrict__ Vl,
              const float* __restrict__ maskp,
              bf16* __restrict__ ctxh, bf16* __restrict__ ctxl)
{
    extern __shared__ bf16 sma[];
    float* mbuf = (float*)(sma + 2 * A_STG);

    const int tid = threadIdx.x;
    const int w = tid >> 5, lane = tid & 31;
    const int g = lane >> 2, t = lane & 3;
    const int h = blockIdx.y, b = blockIdx.z, kh = h >> 2;
    const size_t qrow0 = (size_t)b * SS + blockIdx.x * 64 + w * 16;

    // base-2: fold log2(e) into scale and mask bias
    const float scale2 = 0.08838834764831845f * 1.4426950408889634f;

    auto issue = [&](int kt, int s) {
        bf16* sKh = sma + (size_t)s * A_STG;
        bf16* sKl = sKh + KTILE * KLD;
        bf16* sVh = sKl + KTILE * KLD;
        bf16* sVl = sVh + KTILE * KLD;
        const int kv0 = kt * KTILE;
        const size_t gbase = ((size_t)b * SS + kv0) * KVDIM + kh * HDIM;
        #pragma unroll
        for (int j = 0; j < 4; j++) {
            int id = tid + 128 * j;
            int r = id >> 4, c8 = (id & 15) * 8;
            size_t go = gbase + (size_t)r * KVDIM + c8;
            int so = r * KLD + c8;
            cpa16(sptr(sKh + so), Kh + go);
            cpa16(sptr(sKl + so), Kl + go);
            cpa16(sptr(sVh + so), Vh + go);
            cpa16(sptr(sVl + so), Vl + go);
        }
        if (tid < KTILE)
            mbuf[s * KTILE + tid] =
                (1.0f - maskp[(size_t)b * SS + kv0 + tid]) * -1.4426950408889634e9f;
        CP_COMMIT();
    };

    uint32_t qfh[8][4], qfl[8][4];
    {
        const bf16* qh0 = Qh + qrow0 * EMBED + h * HDIM;
        const bf16* ql0 = Ql + qrow0 * EMBED + h * HDIM;
        #pragma unroll
        for (int kk = 0; kk < 8; kk++) {
            int c0 = 16 * kk + 2 * t;
            qfh[kk][0] = *(const uint32_t*)(qh0 + (size_t)g * EMBED + c0);
            qfh[kk][1] = *(const uint32_t*)(qh0 + (size_t)(g + 8) * EMBED + c0);
            qfh[kk][2] = *(const uint32_t*)(qh0 + (size_t)g * EMBED + c0 + 8);
            qfh[kk][3] = *(const uint32_t*)(qh0 + (size_t)(g + 8) * EMBED + c0 + 8);
            qfl[kk][0] = *(const uint32_t*)(ql0 + (size_t)g * EMBED + c0);
            qfl[kk][1] = *(const uint32_t*)(ql0 + (size_t)(g + 8) * EMBED + c0);
            qfl[kk][2] = *(const uint32_t*)(ql0 + (size_t)g * EMBED + c0 + 8);
            qfl[kk][3] = *(const uint32_t*)(ql0 + (size_t)(g + 8) * EMBED + c0 + 8);
        }
    }

    float o[16][4];
    #pragma unroll
    for (int nt = 0; nt < 16; nt++)
        #pragma unroll
        for (int i = 0; i < 4; i++) o[nt][i] = 0.f;
    float m0 = -1e30f, m1 = -1e30f, l0 = 0.f, l1 = 0.f;

    const int vrow = (lane & 7) + (lane & 8);
    const int vsel = (lane & 16) >> 1;

    issue(0, 0);

    const int NKT = SS / KTILE;
    for (int kt = 0; kt < NKT; kt++) {
        const int s = kt & 1;
        CP_WAIT(0);
        __syncthreads();
        // safe: all warps finished compute(kt-1), the only reader of stage s^1
        if (kt + 1 < NKT) issue(kt + 1, s ^ 1);

        bf16* sKh = sma + (size_t)s * A_STG;
        bf16* sKl = sKh + KTILE * KLD;
        bf16* sVh = sKl + KTILE * KLD;
        bf16* sVl = sVh + KTILE * KLD;
        float* mb = mbuf + s * KTILE;

        float sc[4][4];
        #pragma unroll
        for (int nt = 0; nt < 4; nt++)
            #pragma unroll
            for (int i = 0; i < 4; i++) sc[nt][i] = 0.f;

        #pragma unroll
        for (int kk = 0; kk < 8; kk++) {
            #pragma unroll
            for (int nt2 = 0; nt2 < 2; nt2++) {
                int row = 16 * nt2 + (lane & 15);
                int col = 16 * kk + (lane >> 4) * 8;
                uint32_t r0, r1, r2, r3, u0, u1, u2, u3;
                ldsm4(r0, r1, r2, r3, sptr(&sKh[row * KLD + col]));
                ldsm4(u0, u1, u2, u3, sptr(&sKl[row * KLD + col]));
                mma_bf16(sc[2*nt2],   qfh[kk], r0, r2);
                mma_bf16(sc[2*nt2+1], qfh[kk], r1, r3);
                mma_bf16(sc[2*nt2],   qfh[kk], u0, u2);
                mma_bf16(sc[2*nt2+1], qfh[kk], u1, u3);
                mma_bf16(sc[2*nt2],   qfl[kk], r0, r2);
                mma_bf16(sc[2*nt2+1], qfl[kk], r1, r3);
            }
        }

        // ---- scale + mask + online softmax (base-2) ----
        float rm0 = -1e30f, rm1 = -1e30f;
        #pragma unroll
        for (int nt = 0; nt < 4; nt++) {
            float cb0 = mb[8 * nt + 2 * t];
            float cb1 = mb[8 * nt + 2 * t + 1];
            sc[nt][0] = sc[nt][0] * scale2 + cb0;
            sc[nt][1] = sc[nt][1] * scale2 + cb1;
            sc[nt][2] = sc[nt][2] * scale2 + cb0;
            sc[nt][3] = sc[nt][3] * scale2 + cb1;
            rm0 = fmaxf(rm0, fmaxf(sc[nt][0], sc[nt][1]));
            rm1 = fmaxf(rm1, fmaxf(sc[nt][2], sc[nt][3]));
        }
        rm0 = fmaxf(rm0, __shfl_xor_sync(0xffffffffu, rm0, 1));
        rm0 = fmaxf(rm0, __shfl_xor_sync(0xffffffffu, rm0, 2));
        rm1 = fmaxf(rm1, __shfl_xor_sync(0xffffffffu, rm1, 1));
        rm1 = fmaxf(rm1, __shfl_xor_sync(0xffffffffu, rm1, 2));
        float mn0 = fmaxf(m0, rm0), mn1 = fmaxf(m1, rm1);
        float a0 = ex2(m0 - mn0), a1 = ex2(m1 - mn1);
        m0 = mn0; m1 = mn1;

        float ps0 = 0.f, ps1 = 0.f;
        #pragma unroll
        for (int nt = 0; nt < 4; nt++) {
            sc[nt][0] = ex2(sc[nt][0] - mn0);
            sc[nt][1] = ex2(sc[nt][1] - mn0);
            sc[nt][2] = ex2(sc[nt][2] - mn1);
            sc[nt][3] = ex2(sc[nt][3] - mn1);
            ps0 += sc[nt][0] + sc[nt][1];
            ps1 += sc[nt][2] + sc[nt][3];
        }
        ps0 += __shfl_xor_sync(0xffffffffu, ps0, 1);
        ps0 += __shfl_xor_sync(0xffffffffu, ps0, 2);
        ps1 += __shfl_xor_sync(0xffffffffu, ps1, 1);
        ps1 += __shfl_xor_sync(0xffffffffu, ps1, 2);
        l0 = l0 * a0 + ps0;
        l1 = l1 * a1 + ps1;

        #pragma unroll
        for (int nt = 0; nt < 16; nt++) {
            o[nt][0] *= a0; o[nt][1] *= a0;
            o[nt][2] *= a1; o[nt][3] *= a1;
        }

        uint32_t pah[2][4], pal[2][4];
        #pragma unroll
        for (int j = 0; j < 2; j++) {
            #pragma unroll
            for (int half = 0; half < 2; half++) {
                float v0 = sc[2*j + half][0], v1 = sc[2*j + half][1];
                float v2 = sc[2*j + half][2], v3 = sc[2*j + half][3];
                float h0 = __bfloat162float(__float2bfloat16_rn(v0));
                float h1 = __bfloat162float(__float2bfloat16_rn(v1));
                float h2 = __bfloat162float(__float2bfloat16_rn(v2));
                float h3 = __bfloat162float(__float2bfloat16_rn(v3));
                pah[j][2*half + 0] = packbf2(h0, h1);
                pah[j][2*half + 1] = packbf2(h2, h3);
                pal[j][2*half + 0] = packbf2(v0 - h0, v1 - h1);
                pal[j][2*half + 1] = packbf2(v2 - h2, v3 - h3);
            }
        }

        #pragma unroll
        for (int j = 0; j < 2; j++) {
            #pragma unroll
            for (int nt2 = 0; nt2 < 8; nt2++) {
                int row = 16 * j + vrow;
                int col = 16 * nt2 + vsel;
                uint32_t r0, r1, r2, r3, u0, u1, u2, u3;
                ldsm4t(r0, r1, r2, r3, sptr(&sVh[row * KLD + col]));
                ldsm4t(u0, u1, u2, u3, sptr(&sVl[row * KLD + col]));
                mma_bf16(o[2*nt2],   pah[j], r0, r1);
                mma_bf16(o[2*nt2+1], pah[j], r2, r3);
                mma_bf16(o[2*nt2],   pah[j], u0, u1);
                mma_bf16(o[2*nt2+1], pah[j], u2, u3);
                mma_bf16(o[2*nt2],   pal[j], r0, r1);
                mma_bf16(o[2*nt2+1], pal[j], r2, r3);
            }
        }
    }

    float i0 = 1.0f / l0, i1 = 1.0f / l1;
    size_t base0 = (qrow0 + g) * EMBED + h * HDIM + 2 * t;
    size_t base1 = (qrow0 + g + 8) * EMBED + h * HDIM + 2 * t;
    #pragma unroll
    for (int nt = 0; nt < 16; nt++) {
        split_store2(o[nt][0] * i0, o[nt][1] * i0, &ctxh[base0 + 8 * nt], &ctxl[base0 + 8 * nt]);
        split_store2(o[nt][2] * i1, o[nt][3] * i1, &ctxh[base1 + 8 * nt], &ctxl[base1 + 8 * nt]);
    }
}

// ============================================================
// launcher
// ============================================================
extern "C" void kernel_launch(void* const* d_in, const int* in_sizes, int n_in,
                              void* d_out, int out_size)
{
    const float* query = (const float*)d_in[0];
    const float* key   = (const float*)d_in[1];
    const float* value = (const float*)d_in[2];
    const float* mask  = (const float*)d_in[3];
    const float* Wq    = (const float*)d_in[4];
    const float* Wk    = (const float*)d_in[5];
    const float* Wv    = (const float*)d_in[6];
    const float* Wo    = (const float*)d_in[7];
    float* out = (float*)d_out;

    bf16 *inh, *inl, *wh, *wl, *qh, *ql, *kh, *kl, *vh, *vl, *ctxh, *ctxl;
    cudaGetSymbolAddress((void**)&inh, g_inh);
    cudaGetSymbolAddress((void**)&inl, g_inl);
    cudaGetSymbolAddress((void**)&wh,  g_wh);
    cudaGetSymbolAddress((void**)&wl,  g_wl);
    cudaGetSymbolAddress((void**)&qh,  g_qh);
    cudaGetSymbolAddress((void**)&ql,  g_ql);
    cudaGetSymbolAddress((void**)&kh,  g_kh);
    cudaGetSymbolAddress((void**)&kl,  g_kl);
    cudaGetSymbolAddress((void**)&vh,  g_vh);
    cudaGetSymbolAddress((void**)&vl,  g_vl);
    cudaGetSymbolAddress((void**)&ctxh, g_ctxh);
    cudaGetSymbolAddress((void**)&ctxl, g_ctxl);

    cudaFuncSetAttribute(attn_mma, cudaFuncAttributeMaxDynamicSharedMemorySize, ATTN_SMEM);
    cudaFuncSetAttribute(gemm_proj, cudaFuncAttributeMaxDynamicSharedMemorySize, GEMM_SMEM);
    cudaFuncSetAttribute(gemm_out,  cudaFuncAttributeMaxDynamicSharedMemorySize, GEMM_SMEM);

    dim3 blk(256);

    // ---- fused split pass ----
    {
        SplitArgs a;
        a.src[0] = query; a.dh[0] = inh + 0 * (size_t)IN_STRIDE; a.dl[0] = inl + 0 * (size_t)IN_STRIDE;
        a.src[1] = key;   a.dh[1] = inh + 1 * (size_t)IN_STRIDE; a.dl[1] = inl + 1 * (size_t)IN_STRIDE;
        a.src[2] = value; a.dh[2] = inh + 2 * (size_t)IN_STRIDE; a.dl[2] = inl + 2 * (size_t)IN_STRIDE;
        a.src[3] = Wq;    a.dh[3] = wh + WQ_OFF;                 a.dl[3] = wl + WQ_OFF;
        a.src[4] = Wk;    a.dh[4] = wh + WK_OFF;                 a.dl[4] = wl + WK_OFF;
        a.src[5] = Wv;    a.dh[5] = wh + WV_OFF;                 a.dl[5] = wl + WV_OFF;
        a.src[6] = Wo;    a.dh[6] = wh + WO_OFF;                 a.dl[6] = wl + WO_OFF;
        fused_split<<<SPLIT_BLOCKS, blk>>>(a);
    }

    // ---- fused Q/K/V projections ----
    {
        ProjArgs p;
        p.Ah[0] = inh + 0 * (size_t)IN_STRIDE; p.Al[0] = inl + 0 * (size_t)IN_STRIDE;
        p.Ah[1] = inh + 1 * (size_t)IN_STRIDE; p.Al[1] = inl + 1 * (size_t)IN_STRIDE;
        p.Ah[2] = inh + 2 * (size_t)IN_STRIDE; p.Al[2] = inl + 2 * (size_t)IN_STRIDE;
        p.Bh[0] = wh + WQ_OFF; p.Bl[0] = wl + WQ_OFF;
        p.Bh[1] = wh + WK_OFF; p.Bl[1] = wl + WK_OFF;
        p.Bh[2] = wh + WV_OFF; p.Bl[2] = wl + WV_OFF;
        p.Ch[0] = qh; p.Cl[0] = ql;
        p.Ch[1] = kh; p.Cl[1] = kl;
        p.Ch[2] = vh; p.Cl[2] = vl;
        gemm_proj<<<768, blk, GEMM_SMEM>>>(p);
    }

    // ---- fused attention (4 warps/CTA, 3 CTAs/SM) ----
    attn_mma<<<dim3(SS / 64, NHEAD, BB), dim3(128), ATTN_SMEM>>>(
        qh, ql, kh, kl, vh, vl, mask, ctxh, ctxl);

    // ---- output projection ----
    gemm_out<<<dim3(EMBED / 128, MROWS / 128), blk, GEMM_SMEM>>>(
        ctxh, ctxl, wh + WO_OFF, wl + WO_OFF, out);
}

// round 15
// speedup vs baseline: 1.0223x; 1.0223x over previous
#include <cuda_runtime.h>
#include <cuda_bf16.h>
#include <cstdint>

// Problem constants
#define EMBED 2048
#define NHEAD 16
#define NKV   4
#define HDIM  128
#define BB    2
#define SS    2048
#define MROWS (BB*SS)          // 4096
#define KVDIM (NKV*HDIM)       // 512

typedef __nv_bfloat16 bf16;

// -------- scratch (no allocation allowed) --------
#define IN_STRIDE (MROWS * EMBED)
__device__ bf16 g_inh[3 * IN_STRIDE];
__device__ bf16 g_inl[3 * IN_STRIDE];
#define WQ_OFF 0
#define WK_OFF (EMBED*EMBED)
#define WV_OFF (WK_OFF + EMBED*KVDIM)
#define WO_OFF (WV_OFF + EMBED*KVDIM)
#define W_TOTAL (WO_OFF + EMBED*EMBED)
__device__ bf16 g_wh[W_TOTAL];
__device__ bf16 g_wl[W_TOTAL];
__device__ bf16 g_qh[MROWS * EMBED];
__device__ bf16 g_ql[MROWS * EMBED];
__device__ bf16 g_kh[MROWS * KVDIM];
__device__ bf16 g_kl[MROWS * KVDIM];
__device__ bf16 g_vh[MROWS * KVDIM];
__device__ bf16 g_vl[MROWS * KVDIM];
__device__ bf16 g_ctxh[MROWS * EMBED];
__device__ bf16 g_ctxl[MROWS * EMBED];

// ======================= helpers =======================
__device__ __forceinline__ uint32_t sptr(const void* p) {
    return (uint32_t)__cvta_generic_to_shared(p);
}
__device__ __forceinline__ void cpa16(uint32_t dst, const void* src) {
    asm volatile("cp.async.cg.shared.global [%0], [%1], 16;" :: "r"(dst), "l"(src));
}
#define CP_COMMIT() asm volatile("cp.async.commit_group;")
#define CP_WAIT(n)  asm volatile("cp.async.wait_group %0;" :: "n"(n))

__device__ __forceinline__ void ldsm4(uint32_t& r0, uint32_t& r1, uint32_t& r2, uint32_t& r3, uint32_t a) {
    asm volatile("ldmatrix.sync.aligned.m8n8.x4.shared.b16 {%0,%1,%2,%3},[%4];"
                 : "=r"(r0), "=r"(r1), "=r"(r2), "=r"(r3) : "r"(a));
}
__device__ __forceinline__ void ldsm4t(uint32_t& r0, uint32_t& r1, uint32_t& r2, uint32_t& r3, uint32_t a) {
    asm volatile("ldmatrix.sync.aligned.m8n8.x4.trans.shared.b16 {%0,%1,%2,%3},[%4];"
                 : "=r"(r0), "=r"(r1), "=r"(r2), "=r"(r3) : "r"(a));
}
__device__ __forceinline__ void mma_bf16(float* c, const uint32_t* a, uint32_t b0, uint32_t b1) {
    asm volatile(
        "mma.sync.aligned.m16n8k16.row.col.f32.bf16.bf16.f32 "
        "{%0,%1,%2,%3},{%4,%5,%6,%7},{%8,%9},{%0,%1,%2,%3};"
        : "+f"(c[0]), "+f"(c[1]), "+f"(c[2]), "+f"(c[3])
        : "r"(a[0]), "r"(a[1]), "r"(a[2]), "r"(a[3]), "r"(b0), "r"(b1));
}
__device__ __forceinline__ uint32_t packbf2(float lo, float hi) {
    uint32_t r;
    asm("cvt.rn.bf16x2.f32 %0, %1, %2;" : "=r"(r) : "f"(hi), "f"(lo));
    return r;
}
__device__ __forceinline__ float ex2(float x) {
    float r;
    asm("ex2.approx.ftz.f32 %0, %1;" : "=f"(r) : "f"(x));
    return r;
}
__device__ __forceinline__ void split_store4(float4 v, bf16* ph, bf16* pl) {
    bf16 h0 = __float2bfloat16_rn(v.x), h1 = __float2bfloat16_rn(v.y),
         h2 = __float2bfloat16_rn(v.z), h3 = __float2bfloat16_rn(v.w);
    ((__nv_bfloat162*)ph)[0] = __halves2bfloat162(h0, h1);
    ((__nv_bfloat162*)ph)[1] = __halves2bfloat162(h2, h3);
    ((__nv_bfloat162*)pl)[0] = __floats2bfloat162_rn(v.x - __bfloat162float(h0), v.y - __bfloat162float(h1));
    ((__nv_bfloat162*)pl)[1] = __floats2bfloat162_rn(v.z - __bfloat162float(h2), v.w - __bfloat162float(h3));
}
__device__ __forceinline__ void split_store2(float v0, float v1, bf16* ph, bf16* pl) {
    bf16 h0 = __float2bfloat16_rn(v0), h1 = __float2bfloat16_rn(v1);
    *(__nv_bfloat162*)ph = __halves2bfloat162(h0, h1);
    *(__nv_bfloat162*)pl = __floats2bfloat162_rn(v0 - __bfloat162float(h0), v1 - __bfloat162float(h1));
}

// ============================================================
// fused split: all 7 tensors in one launch
// ============================================================
struct SplitArgs {
    const float* src[7];
    bf16* dh[7];
    bf16* dl[7];
};
#define SPLIT_BLOCKS 34816

__global__ __launch_bounds__(256)
void fused_split(SplitArgs a)
{
    int idx = blockIdx.x * 256 + threadIdx.x;   // float4 index
    int seg, off;
    if (idx < 6291456) {                         // query/key/value
        seg = idx / 2097152; off = idx - seg * 2097152;
    } else if (idx < 7340032) { seg = 3; off = idx - 6291456; }
    else if (idx < 7602176)   { seg = 4; off = idx - 7340032; }
    else if (idx < 7864320)   { seg = 5; off = idx - 7602176; }
    else                      { seg = 6; off = idx - 7864320; }
    float4 v = ((const float4*)a.src[seg])[off];
    split_store4(v, a.dh[seg] + (size_t)off * 4, a.dl[seg] + (size_t)off * 4);
}

// ============================================================
// GEMM tile body
// BM=BN=128, BK=32, 256 threads, 3-stage cp.async, 2 CTAs/SM.
// Single __syncthreads per K-step (issue hoisted behind barrier).
// ============================================================
#define ALD 40
#define BLD 136
#define G_A_ELEMS (128*ALD)
#define G_B_ELEMS (32*BLD)
#define G_STG (2*G_A_ELEMS + 2*G_B_ELEMS)
#define GEMM_SMEM (3 * G_STG * 2)

template<typename EPILOGUE>
__device__ __forceinline__ void gemm_tile(
    const bf16* __restrict__ Ah_g, const bf16* __restrict__ Al_g,
    const bf16* __restrict__ Bh_g, const bf16* __restrict__ Bl_g,
    int N, int K, int bm, int bn, bf16* smg, EPILOGUE epi)
{
    const int tid = threadIdx.x;
    const size_t aBase = (size_t)bm * 128 * K;
    const size_t bBase = (size_t)bn * 128;

    const int w = tid >> 5, lane = tid & 31;
    const int m0w = (w >> 2) * 64, n0w = (w & 3) * 32;
    const int arow = lane & 15, asel = (lane >> 4) * 8;
    const int brow = (lane & 7) + (lane & 8);
    const int bsel = (lane & 16) >> 1;

    float acc[4][4][4];
    #pragma unroll
    for (int mt = 0; mt < 4; mt++)
        #pragma unroll
        for (int nt = 0; nt < 4; nt++)
            #pragma unroll
            for (int i = 0; i < 4; i++) acc[mt][nt][i] = 0.f;

    const int nk = K / 32;

    auto issue = [&](int kt, int s) {
        bf16* sAh = smg + (size_t)s * G_STG;
        bf16* sAl = sAh + G_A_ELEMS;
        bf16* sBh = sAl + G_A_ELEMS;
        bf16* sBl = sBh + G_B_ELEMS;
        const int k0 = kt * 32;
        #pragma unroll
        for (int j = 0; j < 2; j++) {
            int c = tid + 256 * j;
            int r = c >> 2, kc = (c & 3) * 8;
            size_t go = aBase + (size_t)r * K + k0 + kc;
            int so = r * ALD + kc;
            cpa16(sptr(sAh + so), Ah_g + go);
            cpa16(sptr(sAl + so), Al_g + go);
        }
        #pragma unroll
        for (int j = 0; j < 2; j++) {
            int c = tid + 256 * j;
            int r = c >> 4, nc = (c & 15) * 8;
            size_t go = bBase + (size_t)(k0 + r) * N + nc;
            int so = r * BLD + nc;
            cpa16(sptr(sBh + so), Bh_g + go);
            cpa16(sptr(sBl + so), Bl_g + go);
        }
        CP_COMMIT();
    };

    issue(0, 0);
    if (nk > 1) issue(1, 1);

    for (int kt = 0; kt < nk; kt++) {
        const int s = kt % 3;
        if (kt + 1 < nk) { CP_WAIT(1); } else { CP_WAIT(0); }
        __syncthreads();
        // safe: all warps finished compute(kt-1), the only reader of stage (kt+2)%3
        if (kt + 2 < nk) issue(kt + 2, (kt + 2) % 3);

        bf16* sAh = smg + (size_t)s * G_STG;
        bf16* sAl = sAh + G_A_ELEMS;
        bf16* sBh = sAl + G_A_ELEMS;
        bf16* sBl = sBh + G_B_ELEMS;

        #pragma unroll
        for (int kk = 0; kk < 2; kk++) {
            uint32_t ah[4][4], al[4][4];
            #pragma unroll
            for (int mt = 0; mt < 4; mt++) {
                int off = (m0w + 16 * mt + arow) * ALD + 16 * kk + asel;
                ldsm4(ah[mt][0], ah[mt][1], ah[mt][2], ah[mt][3], sptr(&sAh[off]));
                ldsm4(al[mt][0], al[mt][1], al[mt][2], al[mt][3], sptr(&sAl[off]));
            }
            uint32_t bh[4][2], bl[4][2];
            #pragma unroll
            for (int nt2 = 0; nt2 < 2; nt2++) {
                int off = (16 * kk + brow) * BLD + n0w + 16 * nt2 + bsel;
                uint32_t r0, r1, r2, r3;
                ldsm4t(r0, r1, r2, r3, sptr(&sBh[off]));
                bh[2*nt2][0] = r0; bh[2*nt2][1] = r1; bh[2*nt2+1][0] = r2; bh[2*nt2+1][1] = r3;
                ldsm4t(r0, r1, r2, r3, sptr(&sBl[off]));
                bl[2*nt2][0] = r0; bl[2*nt2][1] = r1; bl[2*nt2+1][0] = r2; bl[2*nt2+1][1] = r3;
            }
            #pragma unroll
            for (int mt = 0; mt < 4; mt++)
                #pragma unroll
                for (int nt = 0; nt < 4; nt++) {
                    mma_bf16(acc[mt][nt], ah[mt], bh[nt][0], bh[nt][1]);
                    mma_bf16(acc[mt][nt], ah[mt], bl[nt][0], bl[nt][1]);
                    mma_bf16(acc[mt][nt], al[mt], bh[nt][0], bh[nt][1]);
                }
        }
    }

    const int g = lane >> 2, t = lane & 3;
    #pragma unroll
    for (int mt = 0; mt < 4; mt++)
        #pragma unroll
        for (int nt = 0; nt < 4; nt++) {
            size_t r0 = (size_t)bm * 128 + m0w + 16 * mt + g;
            size_t c0 = (size_t)bn * 128 + n0w + 8 * nt + 2 * t;
            epi(r0, c0, acc[mt][nt][0], acc[mt][nt][1]);
            epi(r0 + 8, c0, acc[mt][nt][2], acc[mt][nt][3]);
        }
}

// ---- fused Q/K/V projection ----
struct ProjArgs {
    const bf16* Ah[3]; const bf16* Al[3];
    const bf16* Bh[3]; const bf16* Bl[3];
    bf16* Ch[3]; bf16* Cl[3];
};

__global__ __launch_bounds__(256, 2)
void gemm_proj(ProjArgs p)
{
    extern __shared__ bf16 smg[];
    int bid = blockIdx.x;
    int gsel, bm, bn, N;
    if (bid < 512) {
        gsel = 0; bm = bid >> 4; bn = bid & 15; N = EMBED;
    } else {
        int u = bid - 512;
        gsel = 1 + (u >> 7);
        u &= 127;
        bm = u >> 2; bn = u & 3; N = KVDIM;
    }
    bf16* Ch = p.Ch[gsel];
    bf16* Cl = p.Cl[gsel];
    gemm_tile(p.Ah[gsel], p.Al[gsel], p.Bh[gsel], p.Bl[gsel], N, EMBED, bm, bn, smg,
        [&](size_t r, size_t c, float v0, float v1) {
            split_store2(v0, v1, &Ch[r * N + c], &Cl[r * N + c]);
        });
}

// ---- O projection: fp32 out ----
__global__ __launch_bounds__(256, 2)
void gemm_out(const bf16* __restrict__ Ah_g, const bf16* __restrict__ Al_g,
              const bf16* __restrict__ Bh_g, const bf16* __restrict__ Bl_g,
              float* __restrict__ Cf)
{
    extern __shared__ bf16 smg[];
    int bm = blockIdx.y, bn = blockIdx.x;
    gemm_tile(Ah_g, Al_g, Bh_g, Bl_g, EMBED, EMBED, bm, bn, smg,
        [&](size_t r, size_t c, float v0, float v1) {
            float2 u; u.x = v0; u.y = v1;
            *(float2*)&Cf[r * EMBED + c] = u;
        });
}

// ============================================================
// Flash attention, bf16-split mma.sync, base-2 softmax.
// 128 threads (4 warps), 64 q-rows/CTA, KV tile 32, 2 CTAs/SM.
// 3-stage cp.async pipeline, single __syncthreads per KV tile.
// smem = 3 * 34.8KB + masks = 105KB <= 114KB/CTA at occ 2.
// ============================================================
#define KTILE 32
#define KLD 136
#define A_STG (4 * KTILE * KLD)
#define ATTN_SMEM (3 * A_STG * 2 + 3 * KTILE * 4)

__global__ __launch_bounds__(128, 2)
void attn_mma(const bf16* __restrict__ Qh, const bf16* __restrict__ Ql,
              const bf16* __restrict__ Kh, const bf16* __restrict__ Kl,
              const bf16* __restrict__ Vh, const bf16* __restrict__ Vl,
              const float* __restrict__ maskp,
              bf16* __restrict__ ctxh, bf16* __restrict__ ctxl)
{
    extern __shared__ bf16 sma[];
    float* mbuf = (float*)(sma + 3 * A_STG);   // [3][KTILE]

    const int tid = threadIdx.x;
    const int w = tid >> 5, lane = tid & 31;
    const int g = lane >> 2, t = lane & 3;
    const int h = blockIdx.y, b = blockIdx.z, kh = h >> 2;
    const size_t qrow0 = (size_t)b * SS + blockIdx.x * 64 + w * 16;

    // base-2: fold log2(e) into scale and mask bias
    const float scale2 = 0.08838834764831845f * 1.4426950408889634f;

    auto issue = [&](int kt, int s) {
        bf16* sKh = sma + (size_t)s * A_STG;
        bf16* sKl = sKh + KTILE * KLD;
        bf16* sVh = sKl + KTILE * KLD;
        bf16* sVl = sVh + KTILE * KLD;
        const int kv0 = kt * KTILE;
        const size_t gbase = ((size_t)b * SS + kv0) * KVDIM + kh * HDIM;
        #pragma unroll
        for (int j = 0; j < 4; j++) {
            int id = tid + 128 * j;
            int r = id >> 4, c8 = (id & 15) * 8;
            size_t go = gbase + (size_t)r * KVDIM + c8;
            int so = r * KLD + c8;
            cpa16(sptr(sKh + so), Kh + go);
            cpa16(sptr(sKl + so), Kl + go);
            cpa16(sptr(sVh + so), Vh + go);
            cpa16(sptr(sVl + so), Vl + go);
        }
        if (tid < KTILE)
            mbuf[s * KTILE + tid] =
                (1.0f - maskp[(size_t)b * SS + kv0 + tid]) * -1.4426950408889634e9f;
        CP_COMMIT();
    };

    uint32_t qfh[8][4], qfl[8][4];
    {
        const bf16* qh0 = Qh + qrow0 * EMBED + h * HDIM;
        const bf16* ql0 = Ql + qrow0 * EMBED + h * HDIM;
        #pragma unroll
        for (int kk = 0; kk < 8; kk++) {
            int c0 = 16 * kk + 2 * t;
            qfh[kk][0] = *(const uint32_t*)(qh0 + (size_t)g * EMBED + c0);
            qfh[kk][1] = *(const uint32_t*)(qh0 + (size_t)(g + 8) * EMBED + c0);
            qfh[kk][2] = *(const uint32_t*)(qh0 + (size_t)g * EMBED + c0 + 8);
            qfh[kk][3] = *(const uint32_t*)(qh0 + (size_t)(g + 8) * EMBED + c0 + 8);
            qfl[kk][0] = *(const uint32_t*)(ql0 + (size_t)g * EMBED + c0);
            qfl[kk][1] = *(const uint32_t*)(ql0 + (size_t)(g + 8) * EMBED + c0);
            qfl[kk][2] = *(const uint32_t*)(ql0 + (size_t)g * EMBED + c0 + 8);
            qfl[kk][3] = *(const uint32_t*)(ql0 + (size_t)(g + 8) * EMBED + c0 + 8);
        }
    }

    float o[16][4];
    #pragma unroll
    for (int nt = 0; nt < 16; nt++)
        #pragma unroll
        for (int i = 0; i < 4; i++) o[nt][i] = 0.f;
    float m0 = -1e30f, m1 = -1e30f, l0 = 0.f, l1 = 0.f;

    const int vrow = (lane & 7) + (lane & 8);
    const int vsel = (lane & 16) >> 1;

    issue(0, 0);
    issue(1, 1);

    const int NKT = SS / KTILE;
    for (int kt = 0; kt < NKT; kt++) {
        const int s = kt % 3;
        if (kt + 1 < NKT) { CP_WAIT(1); } else { CP_WAIT(0); }
        __syncthreads();
        // safe: all warps finished compute(kt-1), the only reader of stage (kt+2)%3
        if (kt + 2 < NKT) issue(kt + 2, (kt + 2) % 3);

        bf16* sKh = sma + (size_t)s * A_STG;
        bf16* sKl = sKh + KTILE * KLD;
        bf16* sVh = sKl + KTILE * KLD;
        bf16* sVl = sVh + KTILE * KLD;
        float* mb = mbuf + s * KTILE;

        float sc[4][4];
        #pragma unroll
        for (int nt = 0; nt < 4; nt++)
            #pragma unroll
            for (int i = 0; i < 4; i++) sc[nt][i] = 0.f;

        #pragma unroll
        for (int kk = 0; kk < 8; kk++) {
            #pragma unroll
            for (int nt2 = 0; nt2 < 2; nt2++) {
                int row = 16 * nt2 + (lane & 15);
                int col = 16 * kk + (lane >> 4) * 8;
                uint32_t r0, r1, r2, r3, u0, u1, u2, u3;
                ldsm4(r0, r1, r2, r3, sptr(&sKh[row * KLD + col]));
                ldsm4(u0, u1, u2, u3, sptr(&sKl[row * KLD + col]));
                mma_bf16(sc[2*nt2],   qfh[kk], r0, r2);
                mma_bf16(sc[2*nt2+1], qfh[kk], r1, r3);
                mma_bf16(sc[2*nt2],   qfh[kk], u0, u2);
                mma_bf16(sc[2*nt2+1], qfh[kk], u1, u3);
                mma_bf16(sc[2*nt2],   qfl[kk], r0, r2);
                mma_bf16(sc[2*nt2+1], qfl[kk], r1, r3);
            }
        }

        // ---- scale + mask + online softmax (base-2) ----
        float rm0 = -1e30f, rm1 = -1e30f;
        #pragma unroll
        for (int nt = 0; nt < 4; nt++) {
            float cb0 = mb[8 * nt + 2 * t];
            float cb1 = mb[8 * nt + 2 * t + 1];
            sc[nt][0] = sc[nt][0] * scale2 + cb0;
            sc[nt][1] = sc[nt][1] * scale2 + cb1;
            sc[nt][2] = sc[nt][2] * scale2 + cb0;
            sc[nt][3] = sc[nt][3] * scale2 + cb1;
            rm0 = fmaxf(rm0, fmaxf(sc[nt][0], sc[nt][1]));
            rm1 = fmaxf(rm1, fmaxf(sc[nt][2], sc[nt][3]));
        }
        rm0 = fmaxf(rm0, __shfl_xor_sync(0xffffffffu, rm0, 1));
        rm0 = fmaxf(rm0, __shfl_xor_sync(0xffffffffu, rm0, 2));
        rm1 = fmaxf(rm1, __shfl_xor_sync(0xffffffffu, rm1, 1));
        rm1 = fmaxf(rm1, __shfl_xor_sync(0xffffffffu, rm1, 2));
        float mn0 = fmaxf(m0, rm0), mn1 = fmaxf(m1, rm1);
        float a0 = ex2(m0 - mn0), a1 = ex2(m1 - mn1);
        m0 = mn0; m1 = mn1;

        float ps0 = 0.f, ps1 = 0.f;
        #pragma unroll
        for (int nt = 0; nt < 4; nt++) {
            sc[nt][0] = ex2(sc[nt][0] - mn0);
            sc[nt][1] = ex2(sc[nt][1] - mn0);
            sc[nt][2] = ex2(sc[nt][2] - mn1);
            sc[nt][3] = ex2(sc[nt][3] - mn1);
            ps0 += sc[nt][0] + sc[nt][1];
            ps1 += sc[nt][2] + sc[nt][3];
        }
        ps0 += __shfl_xor_sync(0xffffffffu, ps0, 1);
        ps0 += __shfl_xor_sync(0xffffffffu, ps0, 2);
        ps1 += __shfl_xor_sync(0xffffffffu, ps1, 1);
        ps1 += __shfl_xor_sync(0xffffffffu, ps1, 2);
        l0 = l0 * a0 + ps0;
        l1 = l1 * a1 + ps1;

        #pragma unroll
        for (int nt = 0; nt < 16; nt++) {
            o[nt][0] *= a0; o[nt][1] *= a0;
            o[nt][2] *= a1; o[nt][3] *= a1;
        }

        uint32_t pah[2][4], pal[2][4];
        #pragma unroll
        for (int j = 0; j < 2; j++) {
            #pragma unroll
            for (int half = 0; half < 2; half++) {
                float v0 = sc[2*j + half][0], v1 = sc[2*j + half][1];
                float v2 = sc[2*j + half][2], v3 = sc[2*j + half][3];
                float h0 = __bfloat162float(__float2bfloat16_rn(v0));
                float h1 = __bfloat162float(__float2bfloat16_rn(v1));
                float h2 = __bfloat162float(__float2bfloat16_rn(v2));
                float h3 = __bfloat162float(__float2bfloat16_rn(v3));
                pah[j][2*half + 0] = packbf2(h0, h1);
                pah[j][2*half + 1] = packbf2(h2, h3);
                pal[j][2*half + 0] = packbf2(v0 - h0, v1 - h1);
                pal[j][2*half + 1] = packbf2(v2 - h2, v3 - h3);
            }
        }

        #pragma unroll
        for (int j = 0; j < 2; j++) {
            #pragma unroll
            for (int nt2 = 0; nt2 < 8; nt2++) {
                int row = 16 * j + vrow;
                int col = 16 * nt2 + vsel;
                uint32_t r0, r1, r2, r3, u0, u1, u2, u3;
                ldsm4t(r0, r1, r2, r3, sptr(&sVh[row * KLD + col]));
                ldsm4t(u0, u1, u2, u3, sptr(&sVl[row * KLD + col]));
                mma_bf16(o[2*nt2],   pah[j], r0, r1);
                mma_bf16(o[2*nt2+1], pah[j], r2, r3);
                mma_bf16(o[2*nt2],   pah[j], u0, u1);
                mma_bf16(o[2*nt2+1], pah[j], u2, u3);
                mma_bf16(o[2*nt2],   pal[j], r0, r1);
                mma_bf16(o[2*nt2+1], pal[j], r2, r3);
            }
        }
    }

    float i0 = 1.0f / l0, i1 = 1.0f / l1;
    size_t base0 = (qrow0 + g) * EMBED + h * HDIM + 2 * t;
    size_t base1 = (qrow0 + g + 8) * EMBED + h * HDIM + 2 * t;
    #pragma unroll
    for (int nt = 0; nt < 16; nt++) {
        split_store2(o[nt][0] * i0, o[nt][1] * i0, &ctxh[base0 + 8 * nt], &ctxl[base0 + 8 * nt]);
        split_store2(o[nt][2] * i1, o[nt][3] * i1, &ctxh[base1 + 8 * nt], &ctxl[base1 + 8 * nt]);
    }
}

// ============================================================
// launcher
// ============================================================
extern "C" void kernel_launch(void* const* d_in, const int* in_sizes, int n_in,
                              void* d_out, int out_size)
{
    const float* query = (const float*)d_in[0];
    const float* key   = (const float*)d_in[1];
    const float* value = (const float*)d_in[2];
    const float* mask  = (const float*)d_in[3];
    const float* Wq    = (const float*)d_in[4];
    const float* Wk    = (const float*)d_in[5];
    const float* Wv    = (const float*)d_in[6];
    const float* Wo    = (const float*)d_in[7];
    float* out = (float*)d_out;

    bf16 *inh, *inl, *wh, *wl, *qh, *ql, *kh, *kl, *vh, *vl, *ctxh, *ctxl;
    cudaGetSymbolAddress((void**)&inh, g_inh);
    cudaGetSymbolAddress((void**)&inl, g_inl);
    cudaGetSymbolAddress((void**)&wh,  g_wh);
    cudaGetSymbolAddress((void**)&wl,  g_wl);
    cudaGetSymbolAddress((void**)&qh,  g_qh);
    cudaGetSymbolAddress((void**)&ql,  g_ql);
    cudaGetSymbolAddress((void**)&kh,  g_kh);
    cudaGetSymbolAddress((void**)&kl,  g_kl);
    cudaGetSymbolAddress((void**)&vh,  g_vh);
    cudaGetSymbolAddress((void**)&vl,  g_vl);
    cudaGetSymbolAddress((void**)&ctxh, g_ctxh);
    cudaGetSymbolAddress((void**)&ctxl, g_ctxl);

    cudaFuncSetAttribute(attn_mma, cudaFuncAttributeMaxDynamicSharedMemorySize, ATTN_SMEM);
    cudaFuncSetAttribute(gemm_proj, cudaFuncAttributeMaxDynamicSharedMemorySize, GEMM_SMEM);
    cudaFuncSetAttribute(gemm_out,  cudaFuncAttributeMaxDynamicSharedMemorySize, GEMM_SMEM);

    dim3 blk(256);

    // ---- fused split pass ----
    {
        SplitArgs a;
        a.src[0] = query; a.dh[0] = inh + 0 * (size_t)IN_STRIDE; a.dl[0] = inl + 0 * (size_t)IN_STRIDE;
        a.src[1] = key;   a.dh[1] = inh + 1 * (size_t)IN_STRIDE; a.dl[1] = inl + 1 * (size_t)IN_STRIDE;
        a.src[2] = value; a.dh[2] = inh + 2 * (size_t)IN_STRIDE; a.dl[2] = inl + 2 * (size_t)IN_STRIDE;
        a.src[3] = Wq;    a.dh[3] = wh + WQ_OFF;                 a.dl[3] = wl + WQ_OFF;
        a.src[4] = Wk;    a.dh[4] = wh + WK_OFF;                 a.dl[4] = wl + WK_OFF;
        a.src[5] = Wv;    a.dh[5] = wh + WV_OFF;                 a.dl[5] = wl + WV_OFF;
        a.src[6] = Wo;    a.dh[6] = wh + WO_OFF;                 a.dl[6] = wl + WO_OFF;
        fused_split<<<SPLIT_BLOCKS, blk>>>(a);
    }

    // ---- fused Q/K/V projections ----
    {
        ProjArgs p;
        p.Ah[0] = inh + 0 * (size_t)IN_STRIDE; p.Al[0] = inl + 0 * (size_t)IN_STRIDE;
        p.Ah[1] = inh + 1 * (size_t)IN_STRIDE; p.Al[1] = inl + 1 * (size_t)IN_STRIDE;
        p.Ah[2] = inh + 2 * (size_t)IN_STRIDE; p.Al[2] = inl + 2 * (size_t)IN_STRIDE;
        p.Bh[0] = wh + WQ_OFF; p.Bl[0] = wl + WQ_OFF;
        p.Bh[1] = wh + WK_OFF; p.Bl[1] = wl + WK_OFF;
        p.Bh[2] = wh + WV_OFF; p.Bl[2] = wl + WV_OFF;
        p.Ch[0] = qh; p.Cl[0] = ql;
        p.Ch[1] = kh; p.Cl[1] = kl;
        p.Ch[2] = vh; p.Cl[2] = vl;
        gemm_proj<<<768, blk, GEMM_SMEM>>>(p);
    }

    // ---- fused attention (4 warps/CTA, 2 CTAs/SM, 3-stage) ----
    attn_mma<<<dim3(SS / 64, NHEAD, BB), dim3(128), ATTN_SMEM>>>(
        qh, ql, kh, kl, vh, vl, mask, ctxh, ctxl);

    // ---- output projection ----
    gemm_out<<<dim3(EMBED / 128, MROWS / 128), blk, GEMM_SMEM>>>(
        ctxh, ctxl, wh + WO_OFF, wl + WO_OFF, out);
}

// round 16
// speedup vs baseline: 1.0337x; 1.0111x over previous
#include <cuda_runtime.h>
#include <cuda_bf16.h>
#include <cstdint>

// Problem constants
#define EMBED 2048
#define NHEAD 16
#define NKV   4
#define HDIM  128
#define BB    2
#define SS    2048
#define MROWS (BB*SS)          // 4096
#define KVDIM (NKV*HDIM)       // 512

typedef __nv_bfloat16 bf16;

// -------- scratch (no allocation allowed) --------
#define IN_STRIDE (MROWS * EMBED)
__device__ bf16 g_inh[3 * IN_STRIDE];
__device__ bf16 g_inl[3 * IN_STRIDE];
#define WQ_OFF 0
#define WK_OFF (EMBED*EMBED)
#define WV_OFF (WK_OFF + EMBED*KVDIM)
#define WO_OFF (WV_OFF + EMBED*KVDIM)
#define W_TOTAL (WO_OFF + EMBED*EMBED)
__device__ bf16 g_wh[W_TOTAL];
__device__ bf16 g_wl[W_TOTAL];
__device__ bf16 g_qh[MROWS * EMBED];
__device__ bf16 g_ql[MROWS * EMBED];
__device__ bf16 g_kh[MROWS * KVDIM];
__device__ bf16 g_kl[MROWS * KVDIM];
__device__ bf16 g_vh[MROWS * KVDIM];
__device__ bf16 g_vl[MROWS * KVDIM];
__device__ bf16 g_ctxh[MROWS * EMBED];
__device__ bf16 g_ctxl[MROWS * EMBED];

// ======================= helpers =======================
__device__ __forceinline__ uint32_t sptr(const void* p) {
    return (uint32_t)__cvta_generic_to_shared(p);
}
__device__ __forceinline__ void cpa16(uint32_t dst, const void* src) {
    asm volatile("cp.async.cg.shared.global [%0], [%1], 16;" :: "r"(dst), "l"(src));
}
#define CP_COMMIT() asm volatile("cp.async.commit_group;")
#define CP_WAIT(n)  asm volatile("cp.async.wait_group %0;" :: "n"(n))

__device__ __forceinline__ void ldsm4(uint32_t& r0, uint32_t& r1, uint32_t& r2, uint32_t& r3, uint32_t a) {
    asm volatile("ldmatrix.sync.aligned.m8n8.x4.shared.b16 {%0,%1,%2,%3},[%4];"
                 : "=r"(r0), "=r"(r1), "=r"(r2), "=r"(r3) : "r"(a));
}
__device__ __forceinline__ void ldsm4t(uint32_t& r0, uint32_t& r1, uint32_t& r2, uint32_t& r3, uint32_t a) {
    asm volatile("ldmatrix.sync.aligned.m8n8.x4.trans.shared.b16 {%0,%1,%2,%3},[%4];"
                 : "=r"(r0), "=r"(r1), "=r"(r2), "=r"(r3) : "r"(a));
}
__device__ __forceinline__ void mma_bf16(float* c, const uint32_t* a, uint32_t b0, uint32_t b1) {
    asm volatile(
        "mma.sync.aligned.m16n8k16.row.col.f32.bf16.bf16.f32 "
        "{%0,%1,%2,%3},{%4,%5,%6,%7},{%8,%9},{%0,%1,%2,%3};"
        : "+f"(c[0]), "+f"(c[1]), "+f"(c[2]), "+f"(c[3])
        : "r"(a[0]), "r"(a[1]), "r"(a[2]), "r"(a[3]), "r"(b0), "r"(b1));
}
__device__ __forceinline__ uint32_t packbf2(float lo, float hi) {
    uint32_t r;
    asm("cvt.rn.bf16x2.f32 %0, %1, %2;" : "=r"(r) : "f"(hi), "f"(lo));
    return r;
}
__device__ __forceinline__ float ex2(float x) {
    float r;
    asm("ex2.approx.ftz.f32 %0, %1;" : "=f"(r) : "f"(x));
    return r;
}
__device__ __forceinline__ void split_store4(float4 v, bf16* ph, bf16* pl) {
    bf16 h0 = __float2bfloat16_rn(v.x), h1 = __float2bfloat16_rn(v.y),
         h2 = __float2bfloat16_rn(v.z), h3 = __float2bfloat16_rn(v.w);
    ((__nv_bfloat162*)ph)[0] = __halves2bfloat162(h0, h1);
    ((__nv_bfloat162*)ph)[1] = __halves2bfloat162(h2, h3);
    ((__nv_bfloat162*)pl)[0] = __floats2bfloat162_rn(v.x - __bfloat162float(h0), v.y - __bfloat162float(h1));
    ((__nv_bfloat162*)pl)[1] = __floats2bfloat162_rn(v.z - __bfloat162float(h2), v.w - __bfloat162float(h3));
}
__device__ __forceinline__ void split_store2(float v0, float v1, bf16* ph, bf16* pl) {
    bf16 h0 = __float2bfloat16_rn(v0), h1 = __float2bfloat16_rn(v1);
    *(__nv_bfloat162*)ph = __halves2bfloat162(h0, h1);
    *(__nv_bfloat162*)pl = __floats2bfloat162_rn(v0 - __bfloat162float(h0), v1 - __bfloat162float(h1));
}

// ============================================================
// fused split: all 7 tensors in one launch
// ============================================================
struct SplitArgs {
    const float* src[7];
    bf16* dh[7];
    bf16* dl[7];
};
#define SPLIT_BLOCKS 34816

__global__ __launch_bounds__(256)
void fused_split(SplitArgs a)
{
    int idx = blockIdx.x * 256 + threadIdx.x;   // float4 index
    int seg, off;
    if (idx < 6291456) {                         // query/key/value
        seg = idx / 2097152; off = idx - seg * 2097152;
    } else if (idx < 7340032) { seg = 3; off = idx - 6291456; }
    else if (idx < 7602176)   { seg = 4; off = idx - 7340032; }
    else if (idx < 7864320)   { seg = 5; off = idx - 7602176; }
    else                      { seg = 6; off = idx - 7864320; }
    float4 v = ((const float4*)a.src[seg])[off];
    split_store4(v, a.dh[seg] + (size_t)off * 4, a.dl[seg] + (size_t)off * 4);
}

// ============================================================
// GEMM tile body
// BM=BN=128, BK=32, 256 threads, 3-stage cp.async, 2 CTAs/SM.
// Single __syncthreads per K-step; TERM-MAJOR MMA ordering
// (16 independent accumulators between same-acc reuses).
// ============================================================
#define ALD 40
#define BLD 136
#define G_A_ELEMS (128*ALD)
#define G_B_ELEMS (32*BLD)
#define G_STG (2*G_A_ELEMS + 2*G_B_ELEMS)
#define GEMM_SMEM (3 * G_STG * 2)

template<typename EPILOGUE>
__device__ __forceinline__ void gemm_tile(
    const bf16* __restrict__ Ah_g, const bf16* __restrict__ Al_g,
    const bf16* __restrict__ Bh_g, const bf16* __restrict__ Bl_g,
    int N, int K, int bm, int bn, bf16* smg, EPILOGUE epi)
{
    const int tid = threadIdx.x;
    const size_t aBase = (size_t)bm * 128 * K;
    const size_t bBase = (size_t)bn * 128;

    const int w = tid >> 5, lane = tid & 31;
    const int m0w = (w >> 2) * 64, n0w = (w & 3) * 32;
    const int arow = lane & 15, asel = (lane >> 4) * 8;
    const int brow = (lane & 7) + (lane & 8);
    const int bsel = (lane & 16) >> 1;

    float acc[4][4][4];
    #pragma unroll
    for (int mt = 0; mt < 4; mt++)
        #pragma unroll
        for (int nt = 0; nt < 4; nt++)
            #pragma unroll
            for (int i = 0; i < 4; i++) acc[mt][nt][i] = 0.f;

    const int nk = K / 32;

    auto issue = [&](int kt, int s) {
        bf16* sAh = smg + (size_t)s * G_STG;
        bf16* sAl = sAh + G_A_ELEMS;
        bf16* sBh = sAl + G_A_ELEMS;
        bf16* sBl = sBh + G_B_ELEMS;
        const int k0 = kt * 32;
        #pragma unroll
        for (int j = 0; j < 2; j++) {
            int c = tid + 256 * j;
            int r = c >> 2, kc = (c & 3) * 8;
            size_t go = aBase + (size_t)r * K + k0 + kc;
            int so = r * ALD + kc;
            cpa16(sptr(sAh + so), Ah_g + go);
            cpa16(sptr(sAl + so), Al_g + go);
        }
        #pragma unroll
        for (int j = 0; j < 2; j++) {
            int c = tid + 256 * j;
            int r = c >> 4, nc = (c & 15) * 8;
            size_t go = bBase + (size_t)(k0 + r) * N + nc;
            int so = r * BLD + nc;
            cpa16(sptr(sBh + so), Bh_g + go);
            cpa16(sptr(sBl + so), Bl_g + go);
        }
        CP_COMMIT();
    };

    issue(0, 0);
    if (nk > 1) issue(1, 1);

    for (int kt = 0; kt < nk; kt++) {
        const int s = kt % 3;
        if (kt + 1 < nk) { CP_WAIT(1); } else { CP_WAIT(0); }
        __syncthreads();
        // safe: all warps finished compute(kt-1), the only reader of stage (kt+2)%3
        if (kt + 2 < nk) issue(kt + 2, (kt + 2) % 3);

        bf16* sAh = smg + (size_t)s * G_STG;
        bf16* sAl = sAh + G_A_ELEMS;
        bf16* sBh = sAl + G_A_ELEMS;
        bf16* sBl = sBh + G_B_ELEMS;

        #pragma unroll
        for (int kk = 0; kk < 2; kk++) {
            uint32_t ah[4][4], al[4][4];
            #pragma unroll
            for (int mt = 0; mt < 4; mt++) {
                int off = (m0w + 16 * mt + arow) * ALD + 16 * kk + asel;
                ldsm4(ah[mt][0], ah[mt][1], ah[mt][2], ah[mt][3], sptr(&sAh[off]));
                ldsm4(al[mt][0], al[mt][1], al[mt][2], al[mt][3], sptr(&sAl[off]));
            }
            uint32_t bh[4][2], bl[4][2];
            #pragma unroll
            for (int nt2 = 0; nt2 < 2; nt2++) {
                int off = (16 * kk + brow) * BLD + n0w + 16 * nt2 + bsel;
                uint32_t r0, r1, r2, r3;
                ldsm4t(r0, r1, r2, r3, sptr(&sBh[off]));
                bh[2*nt2][0] = r0; bh[2*nt2][1] = r1; bh[2*nt2+1][0] = r2; bh[2*nt2+1][1] = r3;
                ldsm4t(r0, r1, r2, r3, sptr(&sBl[off]));
                bl[2*nt2][0] = r0; bl[2*nt2][1] = r1; bl[2*nt2+1][0] = r2; bl[2*nt2+1][1] = r3;
            }
            // term-major: 16 independent accumulators between same-acc reuses
            #pragma unroll
            for (int mt = 0; mt < 4; mt++)
                #pragma unroll
                for (int nt = 0; nt < 4; nt++)
                    mma_bf16(acc[mt][nt], ah[mt], bh[nt][0], bh[nt][1]);
            #pragma unroll
            for (int mt = 0; mt < 4; mt++)
                #pragma unroll
                for (int nt = 0; nt < 4; nt++)
                    mma_bf16(acc[mt][nt], ah[mt], bl[nt][0], bl[nt][1]);
            #pragma unroll
            for (int mt = 0; mt < 4; mt++)
                #pragma unroll
                for (int nt = 0; nt < 4; nt++)
                    mma_bf16(acc[mt][nt], al[mt], bh[nt][0], bh[nt][1]);
        }
    }

    const int g = lane >> 2, t = lane & 3;
    #pragma unroll
    for (int mt = 0; mt < 4; mt++)
        #pragma unroll
        for (int nt = 0; nt < 4; nt++) {
            size_t r0 = (size_t)bm * 128 + m0w + 16 * mt + g;
            size_t c0 = (size_t)bn * 128 + n0w + 8 * nt + 2 * t;
            epi(r0, c0, acc[mt][nt][0], acc[mt][nt][1]);
            epi(r0 + 8, c0, acc[mt][nt][2], acc[mt][nt][3]);
        }
}

// ---- fused Q/K/V projection ----
struct ProjArgs {
    const bf16* Ah[3]; const bf16* Al[3];
    const bf16* Bh[3]; const bf16* Bl[3];
    bf16* Ch[3]; bf16* Cl[3];
};

__global__ __launch_bounds__(256, 2)
void gemm_proj(ProjArgs p)
{
    extern __shared__ bf16 smg[];
    int bid = blockIdx.x;
    int gsel, bm, bn, N;
    if (bid < 512) {
        gsel = 0; bm = bid >> 4; bn = bid & 15; N = EMBED;
    } else {
        int u = bid - 512;
        gsel = 1 + (u >> 7);
        u &= 127;
        bm = u >> 2; bn = u & 3; N = KVDIM;
    }
    bf16* Ch = p.Ch[gsel];
    bf16* Cl = p.Cl[gsel];
    gemm_tile(p.Ah[gsel], p.Al[gsel], p.Bh[gsel], p.Bl[gsel], N, EMBED, bm, bn, smg,
        [&](size_t r, size_t c, float v0, float v1) {
            split_store2(v0, v1, &Ch[r * N + c], &Cl[r * N + c]);
        });
}

// ---- O projection: fp32 out ----
__global__ __launch_bounds__(256, 2)
void gemm_out(const bf16* __restrict__ Ah_g, const bf16* __restrict__ Al_g,
              const bf16* __restrict__ Bh_g, const bf16* __restrict__ Bl_g,
              float* __restrict__ Cf)
{
    extern __shared__ bf16 smg[];
    int bm = blockIdx.y, bn = blockIdx.x;
    gemm_tile(Ah_g, Al_g, Bh_g, Bl_g, EMBED, EMBED, bm, bn, smg,
        [&](size_t r, size_t c, float v0, float v1) {
            float2 u; u.x = v0; u.y = v1;
            *(float2*)&Cf[r * EMBED + c] = u;
        });
}

// ============================================================
// Flash attention, bf16-split mma.sync, base-2 softmax.
// 128 threads (4 warps), 64 q-rows/CTA, KV tile 32, 2 CTAs/SM.
// 2-stage cp.async, single __syncthreads per tile.
// Term-major MMA ordering in QK and PV.
// ============================================================
#define KTILE 32
#define KLD 136
#define A_STG (4 * KTILE * KLD)
#define ATTN_SMEM (2 * A_STG * 2 + 2 * KTILE * 4)

__global__ __launch_bounds__(128, 2)
void attn_mma(const bf16* __restrict__ Qh, const bf16* __restrict__ Ql,
              const bf16* __restrict__ Kh, const bf16* __restrict__ Kl,
              const bf16* __restrict__ Vh, const bf16* __restrict__ Vl,
              const float* __restrict__ maskp,
              bf16* __restrict__ ctxh, bf16* __restrict__ ctxl)
{
    extern __shared__ bf16 sma[];
    float* mbuf = (float*)(sma + 2 * A_STG);

    const int tid = threadIdx.x;
    const int w = tid >> 5, lane = tid & 31;
    const int g = lane >> 2, t = lane & 3;
    const int h = blockIdx.y, b = blockIdx.z, kh = h >> 2;
    const size_t qrow0 = (size_t)b * SS + blockIdx.x * 64 + w * 16;

    // base-2: fold log2(e) into scale and mask bias
    const float scale2 = 0.08838834764831845f * 1.4426950408889634f;

    auto issue = [&](int kt, int s) {
        bf16* sKh = sma + (size_t)s * A_STG;
        bf16* sKl = sKh + KTILE * KLD;
        bf16* sVh = sKl + KTILE * KLD;
        bf16* sVl = sVh + KTILE * KLD;
        const int kv0 = kt * KTILE;
        const size_t gbase = ((size_t)b * SS + kv0) * KVDIM + kh * HDIM;
        #pragma unroll
        for (int j = 0; j < 4; j++) {
            int id = tid + 128 * j;
            int r = id >> 4, c8 = (id & 15) * 8;
            size_t go = gbase + (size_t)r * KVDIM + c8;
            int so = r * KLD + c8;
            cpa16(sptr(sKh + so), Kh + go);
            cpa16(sptr(sKl + so), Kl + go);
            cpa16(sptr(sVh + so), Vh + go);
            cpa16(sptr(sVl + so), Vl + go);
        }
        if (tid < KTILE)
            mbuf[s * KTILE + tid] =
                (1.0f - maskp[(size_t)b * SS + kv0 + tid]) * -1.4426950408889634e9f;
        CP_COMMIT();
    };

    uint32_t qfh[8][4], qfl[8][4];
    {
        const bf16* qh0 = Qh + qrow0 * EMBED + h * HDIM;
        const bf16* ql0 = Ql + qrow0 * EMBED + h * HDIM;
        #pragma unroll
        for (int kk = 0; kk < 8; kk++) {
            int c0 = 16 * kk + 2 * t;
            qfh[kk][0] = *(const uint32_t*)(qh0 + (size_t)g * EMBED + c0);
            qfh[kk][1] = *(const uint32_t*)(qh0 + (size_t)(g + 8) * EMBED + c0);
            qfh[kk][2] = *(const uint32_t*)(qh0 + (size_t)g * EMBED + c0 + 8);
            qfh[kk][3] = *(const uint32_t*)(qh0 + (size_t)(g + 8) * EMBED + c0 + 8);
            qfl[kk][0] = *(const uint32_t*)(ql0 + (size_t)g * EMBED + c0);
            qfl[kk][1] = *(const uint32_t*)(ql0 + (size_t)(g + 8) * EMBED + c0);
            qfl[kk][2] = *(const uint32_t*)(ql0 + (size_t)g * EMBED + c0 + 8);
            qfl[kk][3] = *(const uint32_t*)(ql0 + (size_t)(g + 8) * EMBED + c0 + 8);
        }
    }

    float o[16][4];
    #pragma unroll
    for (int nt = 0; nt < 16; nt++)
        #pragma unroll
        for (int i = 0; i < 4; i++) o[nt][i] = 0.f;
    float m0 = -1e30f, m1 = -1e30f, l0 = 0.f, l1 = 0.f;

    const int vrow = (lane & 7) + (lane & 8);
    const int vsel = (lane & 16) >> 1;

    issue(0, 0);

    const int NKT = SS / KTILE;
    for (int kt = 0; kt < NKT; kt++) {
        const int s = kt & 1;
        CP_WAIT(0);
        __syncthreads();
        // safe: all warps finished compute(kt-1), the only reader of stage s^1
        if (kt + 1 < NKT) issue(kt + 1, s ^ 1);

        bf16* sKh = sma + (size_t)s * A_STG;
        bf16* sKl = sKh + KTILE * KLD;
        bf16* sVh = sKl + KTILE * KLD;
        bf16* sVl = sVh + KTILE * KLD;
        float* mb = mbuf + s * KTILE;

        float sc[4][4];
        #pragma unroll
        for (int nt = 0; nt < 4; nt++)
            #pragma unroll
            for (int i = 0; i < 4; i++) sc[nt][i] = 0.f;

        #pragma unroll
        for (int kk = 0; kk < 8; kk++) {
            uint32_t kfh[2][4], kfl[2][4];
            #pragma unroll
            for (int nt2 = 0; nt2 < 2; nt2++) {
                int row = 16 * nt2 + (lane & 15);
                int col = 16 * kk + (lane >> 4) * 8;
                ldsm4(kfh[nt2][0], kfh[nt2][1], kfh[nt2][2], kfh[nt2][3], sptr(&sKh[row * KLD + col]));
                ldsm4(kfl[nt2][0], kfl[nt2][1], kfl[nt2][2], kfl[nt2][3], sptr(&sKl[row * KLD + col]));
            }
            // term-major: 4 independent accs between same-acc reuses
            #pragma unroll
            for (int nt2 = 0; nt2 < 2; nt2++) {
                mma_bf16(sc[2*nt2],   qfh[kk], kfh[nt2][0], kfh[nt2][2]);
                mma_bf16(sc[2*nt2+1], qfh[kk], kfh[nt2][1], kfh[nt2][3]);
            }
            #pragma unroll
            for (int nt2 = 0; nt2 < 2; nt2++) {
                mma_bf16(sc[2*nt2],   qfh[kk], kfl[nt2][0], kfl[nt2][2]);
                mma_bf16(sc[2*nt2+1], qfh[kk], kfl[nt2][1], kfl[nt2][3]);
            }
            #pragma unroll
            for (int nt2 = 0; nt2 < 2; nt2++) {
                mma_bf16(sc[2*nt2],   qfl[kk], kfh[nt2][0], kfh[nt2][2]);
                mma_bf16(sc[2*nt2+1], qfl[kk], kfh[nt2][1], kfh[nt2][3]);
            }
        }

        // ---- scale + mask + online softmax (base-2) ----
        float rm0 = -1e30f, rm1 = -1e30f;
        #pragma unroll
        for (int nt = 0; nt < 4; nt++) {
            float cb0 = mb[8 * nt + 2 * t];
            float cb1 = mb[8 * nt + 2 * t + 1];
            sc[nt][0] = sc[nt][0] * scale2 + cb0;
            sc[nt][1] = sc[nt][1] * scale2 + cb1;
            sc[nt][2] = sc[nt][2] * scale2 + cb0;
            sc[nt][3] = sc[nt][3] * scale2 + cb1;
            rm0 = fmaxf(rm0, fmaxf(sc[nt][0], sc[nt][1]));
            rm1 = fmaxf(rm1, fmaxf(sc[nt][2], sc[nt][3]));
        }
        rm0 = fmaxf(rm0, __shfl_xor_sync(0xffffffffu, rm0, 1));
        rm0 = fmaxf(rm0, __shfl_xor_sync(0xffffffffu, rm0, 2));
        rm1 = fmaxf(rm1, __shfl_xor_sync(0xffffffffu, rm1, 1));
        rm1 = fmaxf(rm1, __shfl_xor_sync(0xffffffffu, rm1, 2));
        float mn0 = fmaxf(m0, rm0), mn1 = fmaxf(m1, rm1);
        float a0 = ex2(m0 - mn0), a1 = ex2(m1 - mn1);
        m0 = mn0; m1 = mn1;

        float ps0 = 0.f, ps1 = 0.f;
        #pragma unroll
        for (int nt = 0; nt < 4; nt++) {
            sc[nt][0] = ex2(sc[nt][0] - mn0);
            sc[nt][1] = ex2(sc[nt][1] - mn0);
            sc[nt][2] = ex2(sc[nt][2] - mn1);
            sc[nt][3] = ex2(sc[nt][3] - mn1);
            ps0 += sc[nt][0] + sc[nt][1];
            ps1 += sc[nt][2] + sc[nt][3];
        }
        ps0 += __shfl_xor_sync(0xffffffffu, ps0, 1);
        ps0 += __shfl_xor_sync(0xffffffffu, ps0, 2);
        ps1 += __shfl_xor_sync(0xffffffffu, ps1, 1);
        ps1 += __shfl_xor_sync(0xffffffffu, ps1, 2);
        l0 = l0 * a0 + ps0;
        l1 = l1 * a1 + ps1;

        #pragma unroll
        for (int nt = 0; nt < 16; nt++) {
            o[nt][0] *= a0; o[nt][1] *= a0;
            o[nt][2] *= a1; o[nt][3] *= a1;
        }

        uint32_t pah[2][4], pal[2][4];
        #pragma unroll
        for (int j = 0; j < 2; j++) {
            #pragma unroll
            for (int half = 0; half < 2; half++) {
                float v0 = sc[2*j + half][0], v1 = sc[2*j + half][1];
                float v2 = sc[2*j + half][2], v3 = sc[2*j + half][3];
                float h0 = __bfloat162float(__float2bfloat16_rn(v0));
                float h1 = __bfloat162float(__float2bfloat16_rn(v1));
                float h2 = __bfloat162float(__float2bfloat16_rn(v2));
                float h3 = __bfloat162float(__float2bfloat16_rn(v3));
                pah[j][2*half + 0] = packbf2(h0, h1);
                pah[j][2*half + 1] = packbf2(h2, h3);
                pal[j][2*half + 0] = packbf2(v0 - h0, v1 - h1);
                pal[j][2*half + 1] = packbf2(v2 - h2, v3 - h3);
            }
        }

        // ---- O += P V, term-major across the 8 nt2 d-tiles ----
        #pragma unroll
        for (int j = 0; j < 2; j++) {
            uint32_t vfh[8][4], vfl[8][4];
            #pragma unroll
            for (int nt2 = 0; nt2 < 8; nt2++) {
                int row = 16 * j + vrow;
                int col = 16 * nt2 + vsel;
                ldsm4t(vfh[nt2][0], vfh[nt2][1], vfh[nt2][2], vfh[nt2][3], sptr(&sVh[row * KLD + col]));
                ldsm4t(vfl[nt2][0], vfl[nt2][1], vfl[nt2][2], vfl[nt2][3], sptr(&sVl[row * KLD + col]));
            }
            #pragma unroll
            for (int nt2 = 0; nt2 < 8; nt2++) {
                mma_bf16(o[2*nt2],   pah[j], vfh[nt2][0], vfh[nt2][1]);
                mma_bf16(o[2*nt2+1], pah[j], vfh[nt2][2], vfh[nt2][3]);
            }
            #pragma unroll
            for (int nt2 = 0; nt2 < 8; nt2++) {
                mma_bf16(o[2*nt2],   pah[j], vfl[nt2][0], vfl[nt2][1]);
                mma_bf16(o[2*nt2+1], pah[j], vfl[nt2][2], vfl[nt2][3]);
            }
            #pragma unroll
            for (int nt2 = 0; nt2 < 8; nt2++) {
                mma_bf16(o[2*nt2],   pal[j], vfh[nt2][0], vfh[nt2][1]);
                mma_bf16(o[2*nt2+1], pal[j], vfh[nt2][2], vfh[nt2][3]);
            }
        }
    }

    float i0 = 1.0f / l0, i1 = 1.0f / l1;
    size_t base0 = (qrow0 + g) * EMBED + h * HDIM + 2 * t;
    size_t base1 = (qrow0 + g + 8) * EMBED + h * HDIM + 2 * t;
    #pragma unroll
    for (int nt = 0; nt < 16; nt++) {
        split_store2(o[nt][0] * i0, o[nt][1] * i0, &ctxh[base0 + 8 * nt], &ctxl[base0 + 8 * nt]);
        split_store2(o[nt][2] * i1, o[nt][3] * i1, &ctxh[base1 + 8 * nt], &ctxl[base1 + 8 * nt]);
    }
}

// ============================================================
// launcher
// ============================================================
extern "C" void kernel_launch(void* const* d_in, const int* in_sizes, int n_in,
                              void* d_out, int out_size)
{
    const float* query = (const float*)d_in[0];
    const float* key   = (const float*)d_in[1];
    const float* value = (const float*)d_in[2];
    const float* mask  = (const float*)d_in[3];
    const float* Wq    = (const float*)d_in[4];
    const float* Wk    = (const float*)d_in[5];
    const float* Wv    = (const float*)d_in[6];
    const float* Wo    = (const float*)d_in[7];
    float* out = (float*)d_out;

    bf16 *inh, *inl, *wh, *wl, *qh, *ql, *kh, *kl, *vh, *vl, *ctxh, *ctxl;
    cudaGetSymbolAddress((void**)&inh, g_inh);
    cudaGetSymbolAddress((void**)&inl, g_inl);
    cudaGetSymbolAddress((void**)&wh,  g_wh);
    cudaGetSymbolAddress((void**)&wl,  g_wl);
    cudaGetSymbolAddress((void**)&qh,  g_qh);
    cudaGetSymbolAddress((void**)&ql,  g_ql);
    cudaGetSymbolAddress((void**)&kh,  g_kh);
    cudaGetSymbolAddress((void**)&kl,  g_kl);
    cudaGetSymbolAddress((void**)&vh,  g_vh);
    cudaGetSymbolAddress((void**)&vl,  g_vl);
    cudaGetSymbolAddress((void**)&ctxh, g_ctxh);
    cudaGetSymbolAddress((void**)&ctxl, g_ctxl);

    cudaFuncSetAttribute(attn_mma, cudaFuncAttributeMaxDynamicSharedMemorySize, ATTN_SMEM);
    cudaFuncSetAttribute(gemm_proj, cudaFuncAttributeMaxDynamicSharedMemorySize, GEMM_SMEM);
    cudaFuncSetAttribute(gemm_out,  cudaFuncAttributeMaxDynamicSharedMemorySize, GEMM_SMEM);

    dim3 blk(256);

    // ---- fused split pass ----
    {
        SplitArgs a;
        a.src[0] = query; a.dh[0] = inh + 0 * (size_t)IN_STRIDE; a.dl[0] = inl + 0 * (size_t)IN_STRIDE;
        a.src[1] = key;   a.dh[1] = inh + 1 * (size_t)IN_STRIDE; a.dl[1] = inl + 1 * (size_t)IN_STRIDE;
        a.src[2] = value; a.dh[2] = inh + 2 * (size_t)IN_STRIDE; a.dl[2] = inl + 2 * (size_t)IN_STRIDE;
        a.src[3] = Wq;    a.dh[3] = wh + WQ_OFF;                 a.dl[3] = wl + WQ_OFF;
        a.src[4] = Wk;    a.dh[4] = wh + WK_OFF;                 a.dl[4] = wl + WK_OFF;
        a.src[5] = Wv;    a.dh[5] = wh + WV_OFF;                 a.dl[5] = wl + WV_OFF;
        a.src[6] = Wo;    a.dh[6] = wh + WO_OFF;                 a.dl[6] = wl + WO_OFF;
        fused_split<<<SPLIT_BLOCKS, blk>>>(a);
    }

    // ---- fused Q/K/V projections ----
    {
        ProjArgs p;
        p.Ah[0] = inh + 0 * (size_t)IN_STRIDE; p.Al[0] = inl + 0 * (size_t)IN_STRIDE;
        p.Ah[1] = inh + 1 * (size_t)IN_STRIDE; p.Al[1] = inl + 1 * (size_t)IN_STRIDE;
        p.Ah[2] = inh + 2 * (size_t)IN_STRIDE; p.Al[2] = inl + 2 * (size_t)IN_STRIDE;
        p.Bh[0] = wh + WQ_OFF; p.Bl[0] = wl + WQ_OFF;
        p.Bh[1] = wh + WK_OFF; p.Bl[1] = wl + WK_OFF;
        p.Bh[2] = wh + WV_OFF; p.Bl[2] = wl + WV_OFF;
        p.Ch[0] = qh; p.Cl[0] = ql;
        p.Ch[1] = kh; p.Cl[1] = kl;
        p.Ch[2] = vh; p.Cl[2] = vl;
        gemm_proj<<<768, blk, GEMM_SMEM>>>(p);
    }

    // ---- fused attention (4 warps/CTA, 2 CTAs/SM, 2-stage) ----
    attn_mma<<<dim3(SS / 64, NHEAD, BB), dim3(128), ATTN_SMEM>>>(
        qh, ql, kh, kl, vh, vl, mask, ctxh, ctxl);

    // ---- output projection ----
    gemm_out<<<dim3(EMBED / 128, MROWS / 128), blk, GEMM_SMEM>>>(
        ctxh, ctxl, wh + WO_OFF, wl + WO_OFF, out);
}

// round 17
// speedup vs baseline: 1.1131x; 1.0768x over previous
#include <cuda_runtime.h>
#include <cuda_bf16.h>
#include <cstdint>

// Problem constants
#define EMBED 2048
#define NHEAD 16
#define NKV   4
#define HDIM  128
#define BB    2
#define SS    2048
#define MROWS (BB*SS)          // 4096
#define KVDIM (NKV*HDIM)       // 512

typedef __nv_bfloat16 bf16;

// -------- scratch (no allocation allowed) --------
#define IN_STRIDE (MROWS * EMBED)
__device__ bf16 g_inh[3 * IN_STRIDE];
__device__ bf16 g_inl[3 * IN_STRIDE];
#define WQ_OFF 0
#define WK_OFF (EMBED*EMBED)
#define WV_OFF (WK_OFF + EMBED*KVDIM)
#define WO_OFF (WV_OFF + EMBED*KVDIM)
#define W_TOTAL (WO_OFF + EMBED*EMBED)
__device__ bf16 g_wh[W_TOTAL];
__device__ bf16 g_wl[W_TOTAL];
__device__ bf16 g_qh[MROWS * EMBED];
__device__ bf16 g_ql[MROWS * EMBED];
__device__ bf16 g_kh[MROWS * KVDIM];
__device__ bf16 g_kl[MROWS * KVDIM];
__device__ bf16 g_vh[MROWS * KVDIM];
__device__ bf16 g_vl[MROWS * KVDIM];
__device__ bf16 g_ctxh[MROWS * EMBED];
__device__ bf16 g_ctxl[MROWS * EMBED];

// ======================= helpers =======================
__device__ __forceinline__ uint32_t sptr(const void* p) {
    return (uint32_t)__cvta_generic_to_shared(p);
}
__device__ __forceinline__ void cpa16(uint32_t dst, const void* src) {
    asm volatile("cp.async.cg.shared.global [%0], [%1], 16;" :: "r"(dst), "l"(src));
}
#define CP_COMMIT() asm volatile("cp.async.commit_group;")
#define CP_WAIT(n)  asm volatile("cp.async.wait_group %0;" :: "n"(n))

__device__ __forceinline__ void ldsm4(uint32_t& r0, uint32_t& r1, uint32_t& r2, uint32_t& r3, uint32_t a) {
    asm volatile("ldmatrix.sync.aligned.m8n8.x4.shared.b16 {%0,%1,%2,%3},[%4];"
                 : "=r"(r0), "=r"(r1), "=r"(r2), "=r"(r3) : "r"(a));
}
__device__ __forceinline__ void ldsm4t(uint32_t& r0, uint32_t& r1, uint32_t& r2, uint32_t& r3, uint32_t a) {
    asm volatile("ldmatrix.sync.aligned.m8n8.x4.trans.shared.b16 {%0,%1,%2,%3},[%4];"
                 : "=r"(r0), "=r"(r1), "=r"(r2), "=r"(r3) : "r"(a));
}
__device__ __forceinline__ void mma_bf16(float* c, const uint32_t* a, uint32_t b0, uint32_t b1) {
    asm volatile(
        "mma.sync.aligned.m16n8k16.row.col.f32.bf16.bf16.f32 "
        "{%0,%1,%2,%3},{%4,%5,%6,%7},{%8,%9},{%0,%1,%2,%3};"
        : "+f"(c[0]), "+f"(c[1]), "+f"(c[2]), "+f"(c[3])
        : "r"(a[0]), "r"(a[1]), "r"(a[2]), "r"(a[3]), "r"(b0), "r"(b1));
}
__device__ __forceinline__ uint32_t packbf2(float lo, float hi) {
    uint32_t r;
    asm("cvt.rn.bf16x2.f32 %0, %1, %2;" : "=r"(r) : "f"(hi), "f"(lo));
    return r;
}
__device__ __forceinline__ float ex2(float x) {
    float r;
    asm("ex2.approx.ftz.f32 %0, %1;" : "=f"(r) : "f"(x));
    return r;
}
__device__ __forceinline__ void split_store4(float4 v, bf16* ph, bf16* pl) {
    bf16 h0 = __float2bfloat16_rn(v.x), h1 = __float2bfloat16_rn(v.y),
         h2 = __float2bfloat16_rn(v.z), h3 = __float2bfloat16_rn(v.w);
    ((__nv_bfloat162*)ph)[0] = __halves2bfloat162(h0, h1);
    ((__nv_bfloat162*)ph)[1] = __halves2bfloat162(h2, h3);
    ((__nv_bfloat162*)pl)[0] = __floats2bfloat162_rn(v.x - __bfloat162float(h0), v.y - __bfloat162float(h1));
    ((__nv_bfloat162*)pl)[1] = __floats2bfloat162_rn(v.z - __bfloat162float(h2), v.w - __bfloat162float(h3));
}
__device__ __forceinline__ void split_store2(float v0, float v1, bf16* ph, bf16* pl) {
    bf16 h0 = __float2bfloat16_rn(v0), h1 = __float2bfloat16_rn(v1);
    *(__nv_bfloat162*)ph = __halves2bfloat162(h0, h1);
    *(__nv_bfloat162*)pl = __floats2bfloat162_rn(v0 - __bfloat162float(h0), v1 - __bfloat162float(h1));
}

// ============================================================
// fused split: all 7 tensors in one launch
// ============================================================
struct SplitArgs {
    const float* src[7];
    bf16* dh[7];
    bf16* dl[7];
};
#define SPLIT_BLOCKS 34816

__global__ __launch_bounds__(256)
void fused_split(SplitArgs a)
{
    int idx = blockIdx.x * 256 + threadIdx.x;   // float4 index
    int seg, off;
    if (idx < 6291456) {                         // query/key/value
        seg = idx / 2097152; off = idx - seg * 2097152;
    } else if (idx < 7340032) { seg = 3; off = idx - 6291456; }
    else if (idx < 7602176)   { seg = 4; off = idx - 7340032; }
    else if (idx < 7864320)   { seg = 5; off = idx - 7602176; }
    else                      { seg = 6; off = idx - 7864320; }
    float4 v = ((const float4*)a.src[seg])[off];
    split_store4(v, a.dh[seg] + (size_t)off * 4, a.dl[seg] + (size_t)off * 4);
}

// ============================================================
// GEMM tile body
// BM=64, BN=128, BK=32, 128 threads (4 warps 1x4, warp tile 64x32),
// 2-stage cp.async, 4 CTAs/SM (independent phase interleave).
// Single __syncthreads per K-step.
// ============================================================
#define ALD 40
#define BLD 136
#define G_A_ELEMS (64*ALD)      // 2560
#define G_B_ELEMS (32*BLD)      // 4352
#define G_STG (2*G_A_ELEMS + 2*G_B_ELEMS)   // 13824 elems/stage
#define GEMM_SMEM (2 * G_STG * 2)           // 55296 bytes

template<typename EPILOGUE>
__device__ __forceinline__ void gemm_tile(
    const bf16* __restrict__ Ah_g, const bf16* __restrict__ Al_g,
    const bf16* __restrict__ Bh_g, const bf16* __restrict__ Bl_g,
    int N, int K, int bm, int bn, bf16* smg, EPILOGUE epi)
{
    const int tid = threadIdx.x;
    const size_t aBase = (size_t)bm * 64 * K;
    const size_t bBase = (size_t)bn * 128;

    const int w = tid >> 5, lane = tid & 31;
    const int n0w = w * 32;
    const int arow = lane & 15, asel = (lane >> 4) * 8;
    const int brow = (lane & 7) + (lane & 8);
    const int bsel = (lane & 16) >> 1;

    float acc[4][4][4];
    #pragma unroll
    for (int mt = 0; mt < 4; mt++)
        #pragma unroll
        for (int nt = 0; nt < 4; nt++)
            #pragma unroll
            for (int i = 0; i < 4; i++) acc[mt][nt][i] = 0.f;

    const int nk = K / 32;

    auto issue = [&](int kt, int s) {
        bf16* sAh = smg + (size_t)s * G_STG;
        bf16* sAl = sAh + G_A_ELEMS;
        bf16* sBh = sAl + G_A_ELEMS;
        bf16* sBl = sBh + G_B_ELEMS;
        const int k0 = kt * 32;
        #pragma unroll
        for (int j = 0; j < 2; j++) {
            int c = tid + 128 * j;            // 0..255: 64 rows x 4 chunks
            int r = c >> 2, kc = (c & 3) * 8;
            size_t go = aBase + (size_t)r * K + k0 + kc;
            int so = r * ALD + kc;
            cpa16(sptr(sAh + so), Ah_g + go);
            cpa16(sptr(sAl + so), Al_g + go);
        }
        #pragma unroll
        for (int j = 0; j < 4; j++) {
            int c = tid + 128 * j;            // 0..511: 32 rows x 16 chunks
            int r = c >> 4, nc = (c & 15) * 8;
            size_t go = bBase + (size_t)(k0 + r) * N + nc;
            int so = r * BLD + nc;
            cpa16(sptr(sBh + so), Bh_g + go);
            cpa16(sptr(sBl + so), Bl_g + go);
        }
        CP_COMMIT();
    };

    issue(0, 0);

    for (int kt = 0; kt < nk; kt++) {
        const int s = kt & 1;
        CP_WAIT(0);
        __syncthreads();
        // safe: all warps finished compute(kt-1), the only reader of stage s^1
        if (kt + 1 < nk) issue(kt + 1, s ^ 1);

        bf16* sAh = smg + (size_t)s * G_STG;
        bf16* sAl = sAh + G_A_ELEMS;
        bf16* sBh = sAl + G_A_ELEMS;
        bf16* sBl = sBh + G_B_ELEMS;

        #pragma unroll
        for (int kk = 0; kk < 2; kk++) {
            uint32_t ah[4][4], al[4][4];
            #pragma unroll
            for (int mt = 0; mt < 4; mt++) {
                int off = (16 * mt + arow) * ALD + 16 * kk + asel;
                ldsm4(ah[mt][0], ah[mt][1], ah[mt][2], ah[mt][3], sptr(&sAh[off]));
                ldsm4(al[mt][0], al[mt][1], al[mt][2], al[mt][3], sptr(&sAl[off]));
            }
            uint32_t bh[4][2], bl[4][2];
            #pragma unroll
            for (int nt2 = 0; nt2 < 2; nt2++) {
                int off = (16 * kk + brow) * BLD + n0w + 16 * nt2 + bsel;
                uint32_t r0, r1, r2, r3;
                ldsm4t(r0, r1, r2, r3, sptr(&sBh[off]));
                bh[2*nt2][0] = r0; bh[2*nt2][1] = r1; bh[2*nt2+1][0] = r2; bh[2*nt2+1][1] = r3;
                ldsm4t(r0, r1, r2, r3, sptr(&sBl[off]));
                bl[2*nt2][0] = r0; bl[2*nt2][1] = r1; bl[2*nt2+1][0] = r2; bl[2*nt2+1][1] = r3;
            }
            #pragma unroll
            for (int mt = 0; mt < 4; mt++)
                #pragma unroll
                for (int nt = 0; nt < 4; nt++) {
                    mma_bf16(acc[mt][nt], ah[mt], bh[nt][0], bh[nt][1]);
                    mma_bf16(acc[mt][nt], ah[mt], bl[nt][0], bl[nt][1]);
                    mma_bf16(acc[mt][nt], al[mt], bh[nt][0], bh[nt][1]);
                }
        }
    }

    const int g = lane >> 2, t = lane & 3;
    #pragma unroll
    for (int mt = 0; mt < 4; mt++)
        #pragma unroll
        for (int nt = 0; nt < 4; nt++) {
            size_t r0 = (size_t)bm * 64 + 16 * mt + g;
            size_t c0 = (size_t)bn * 128 + n0w + 8 * nt + 2 * t;
            epi(r0, c0, acc[mt][nt][0], acc[mt][nt][1]);
            epi(r0 + 8, c0, acc[mt][nt][2], acc[mt][nt][3]);
        }
}

// ---- fused Q/K/V projection: 1536 CTAs (1024 Q + 256 K + 256 V) ----
struct ProjArgs {
    const bf16* Ah[3]; const bf16* Al[3];
    const bf16* Bh[3]; const bf16* Bl[3];
    bf16* Ch[3]; bf16* Cl[3];
};

__global__ __launch_bounds__(128, 4)
void gemm_proj(ProjArgs p)
{
    extern __shared__ bf16 smg[];
    int bid = blockIdx.x;
    int gsel, bm, bn, N;
    if (bid < 1024) {                 // Q: 64 x 16 tiles
        gsel = 0; bm = bid >> 4; bn = bid & 15; N = EMBED;
    } else {                          // K then V: 64 x 4 tiles each
        int u = bid - 1024;
        gsel = 1 + (u >> 8);
        u &= 255;
        bm = u >> 2; bn = u & 3; N = KVDIM;
    }
    bf16* Ch = p.Ch[gsel];
    bf16* Cl = p.Cl[gsel];
    gemm_tile(p.Ah[gsel], p.Al[gsel], p.Bh[gsel], p.Bl[gsel], N, EMBED, bm, bn, smg,
        [&](size_t r, size_t c, float v0, float v1) {
            split_store2(v0, v1, &Ch[r * N + c], &Cl[r * N + c]);
        });
}

// ---- O projection: fp32 out ----
__global__ __launch_bounds__(128, 4)
void gemm_out(const bf16* __restrict__ Ah_g, const bf16* __restrict__ Al_g,
              const bf16* __restrict__ Bh_g, const bf16* __restrict__ Bl_g,
              float* __restrict__ Cf)
{
    extern __shared__ bf16 smg[];
    int bm = blockIdx.y, bn = blockIdx.x;
    gemm_tile(Ah_g, Al_g, Bh_g, Bl_g, EMBED, EMBED, bm, bn, smg,
        [&](size_t r, size_t c, float v0, float v1) {
            float2 u; u.x = v0; u.y = v1;
            *(float2*)&Cf[r * EMBED + c] = u;
        });
}

// ============================================================
// Flash attention, bf16-split mma.sync, base-2 softmax (R13 best).
// 128 threads (4 warps), 64 q-rows/CTA, KV tile 32, 2 CTAs/SM.
// 2-stage cp.async, single __syncthreads per tile.
// ============================================================
#define KTILE 32
#define KLD 136
#define A_STG (4 * KTILE * KLD)
#define ATTN_SMEM (2 * A_STG * 2 + 2 * KTILE * 4)

__global__ __launch_bounds__(128, 2)
void attn_mma(const bf16* __restrict__ Qh, const bf16* __restrict__ Ql,
              const bf16* __restrict__ Kh, const bf16* __restrict__ Kl,
              const bf16* __restrict__ Vh, const bf16* __restrict__ Vl,
              const float* __restrict__ maskp,
              bf16* __restrict__ ctxh, bf16* __restrict__ ctxl)
{
    extern __shared__ bf16 sma[];
    float* mbuf = (float*)(sma + 2 * A_STG);

    const int tid = threadIdx.x;
    const int w = tid >> 5, lane = tid & 31;
    const int g = lane >> 2, t = lane & 3;
    const int h = blockIdx.y, b = blockIdx.z, kh = h >> 2;
    const size_t qrow0 = (size_t)b * SS + blockIdx.x * 64 + w * 16;

    // base-2: fold log2(e) into scale and mask bias
    const float scale2 = 0.08838834764831845f * 1.4426950408889634f;

    auto issue = [&](int kt, int s) {
        bf16* sKh = sma + (size_t)s * A_STG;
        bf16* sKl = sKh + KTILE * KLD;
        bf16* sVh = sKl + KTILE * KLD;
        bf16* sVl = sVh + KTILE * KLD;
        const int kv0 = kt * KTILE;
        const size_t gbase = ((size_t)b * SS + kv0) * KVDIM + kh * HDIM;
        #pragma unroll
        for (int j = 0; j < 4; j++) {
            int id = tid + 128 * j;
            int r = id >> 4, c8 = (id & 15) * 8;
            size_t go = gbase + (size_t)r * KVDIM + c8;
            int so = r * KLD + c8;
            cpa16(sptr(sKh + so), Kh + go);
            cpa16(sptr(sKl + so), Kl + go);
            cpa16(sptr(sVh + so), Vh + go);
            cpa16(sptr(sVl + so), Vl + go);
        }
        if (tid < KTILE)
            mbuf[s * KTILE + tid] =
                (1.0f - maskp[(size_t)b * SS + kv0 + tid]) * -1.4426950408889634e9f;
        CP_COMMIT();
    };

    uint32_t qfh[8][4], qfl[8][4];
    {
        const bf16* qh0 = Qh + qrow0 * EMBED + h * HDIM;
        const bf16* ql0 = Ql + qrow0 * EMBED + h * HDIM;
        #pragma unroll
        for (int kk = 0; kk < 8; kk++) {
            int c0 = 16 * kk + 2 * t;
            qfh[kk][0] = *(const uint32_t*)(qh0 + (size_t)g * EMBED + c0);
            qfh[kk][1] = *(const uint32_t*)(qh0 + (size_t)(g + 8) * EMBED + c0);
            qfh[kk][2] = *(const uint32_t*)(qh0 + (size_t)g * EMBED + c0 + 8);
            qfh[kk][3] = *(const uint32_t*)(qh0 + (size_t)(g + 8) * EMBED + c0 + 8);
            qfl[kk][0] = *(const uint32_t*)(ql0 + (size_t)g * EMBED + c0);
            qfl[kk][1] = *(const uint32_t*)(ql0 + (size_t)(g + 8) * EMBED + c0);
            qfl[kk][2] = *(const uint32_t*)(ql0 + (size_t)g * EMBED + c0 + 8);
            qfl[kk][3] = *(const uint32_t*)(ql0 + (size_t)(g + 8) * EMBED + c0 + 8);
        }
    }

    float o[16][4];
    #pragma unroll
    for (int nt = 0; nt < 16; nt++)
        #pragma unroll
        for (int i = 0; i < 4; i++) o[nt][i] = 0.f;
    float m0 = -1e30f, m1 = -1e30f, l0 = 0.f, l1 = 0.f;

    const int vrow = (lane & 7) + (lane & 8);
    const int vsel = (lane & 16) >> 1;

    issue(0, 0);

    const int NKT = SS / KTILE;
    for (int kt = 0; kt < NKT; kt++) {
        const int s = kt & 1;
        CP_WAIT(0);
        __syncthreads();
        // safe: all warps finished compute(kt-1), the only reader of stage s^1
        if (kt + 1 < NKT) issue(kt + 1, s ^ 1);

        bf16* sKh = sma + (size_t)s * A_STG;
        bf16* sKl = sKh + KTILE * KLD;
        bf16* sVh = sKl + KTILE * KLD;
        bf16* sVl = sVh + KTILE * KLD;
        float* mb = mbuf + s * KTILE;

        float sc[4][4];
        #pragma unroll
        for (int nt = 0; nt < 4; nt++)
            #pragma unroll
            for (int i = 0; i < 4; i++) sc[nt][i] = 0.f;

        #pragma unroll
        for (int kk = 0; kk < 8; kk++) {
            #pragma unroll
            for (int nt2 = 0; nt2 < 2; nt2++) {
                int row = 16 * nt2 + (lane & 15);
                int col = 16 * kk + (lane >> 4) * 8;
                uint32_t r0, r1, r2, r3, u0, u1, u2, u3;
                ldsm4(r0, r1, r2, r3, sptr(&sKh[row * KLD + col]));
                ldsm4(u0, u1, u2, u3, sptr(&sKl[row * KLD + col]));
                mma_bf16(sc[2*nt2],   qfh[kk], r0, r2);
                mma_bf16(sc[2*nt2+1], qfh[kk], r1, r3);
                mma_bf16(sc[2*nt2],   qfh[kk], u0, u2);
                mma_bf16(sc[2*nt2+1], qfh[kk], u1, u3);
                mma_bf16(sc[2*nt2],   qfl[kk], r0, r2);
                mma_bf16(sc[2*nt2+1], qfl[kk], r1, r3);
            }
        }

        // ---- scale + mask + online softmax (base-2) ----
        float rm0 = -1e30f, rm1 = -1e30f;
        #pragma unroll
        for (int nt = 0; nt < 4; nt++) {
            float cb0 = mb[8 * nt + 2 * t];
            float cb1 = mb[8 * nt + 2 * t + 1];
            sc[nt][0] = sc[nt][0] * scale2 + cb0;
            sc[nt][1] = sc[nt][1] * scale2 + cb1;
            sc[nt][2] = sc[nt][2] * scale2 + cb0;
            sc[nt][3] = sc[nt][3] * scale2 + cb1;
            rm0 = fmaxf(rm0, fmaxf(sc[nt][0], sc[nt][1]));
            rm1 = fmaxf(rm1, fmaxf(sc[nt][2], sc[nt][3]));
        }
        rm0 = fmaxf(rm0, __shfl_xor_sync(0xffffffffu, rm0, 1));
        rm0 = fmaxf(rm0, __shfl_xor_sync(0xffffffffu, rm0, 2));
        rm1 = fmaxf(rm1, __shfl_xor_sync(0xffffffffu, rm1, 1));
        rm1 = fmaxf(rm1, __shfl_xor_sync(0xffffffffu, rm1, 2));
        float mn0 = fmaxf(m0, rm0), mn1 = fmaxf(m1, rm1);
        float a0 = ex2(m0 - mn0), a1 = ex2(m1 - mn1);
        m0 = mn0; m1 = mn1;

        float ps0 = 0.f, ps1 = 0.f;
        #pragma unroll
        for (int nt = 0; nt < 4; nt++) {
            sc[nt][0] = ex2(sc[nt][0] - mn0);
            sc[nt][1] = ex2(sc[nt][1] - mn0);
            sc[nt][2] = ex2(sc[nt][2] - mn1);
            sc[nt][3] = ex2(sc[nt][3] - mn1);
            ps0 += sc[nt][0] + sc[nt][1];
            ps1 += sc[nt][2] + sc[nt][3];
        }
        ps0 += __shfl_xor_sync(0xffffffffu, ps0, 1);
        ps0 += __shfl_xor_sync(0xffffffffu, ps0, 2);
        ps1 += __shfl_xor_sync(0xffffffffu, ps1, 1);
        ps1 += __shfl_xor_sync(0xffffffffu, ps1, 2);
        l0 = l0 * a0 + ps0;
        l1 = l1 * a1 + ps1;

        #pragma unroll
        for (int nt = 0; nt < 16; nt++) {
            o[nt][0] *= a0; o[nt][1] *= a0;
            o[nt][2] *= a1; o[nt][3] *= a1;
        }

        uint32_t pah[2][4], pal[2][4];
        #pragma unroll
        for (int j = 0; j < 2; j++) {
            #pragma unroll
            for (int half = 0; half < 2; half++) {
                float v0 = sc[2*j + half][0], v1 = sc[2*j + half][1];
                float v2 = sc[2*j + half][2], v3 = sc[2*j + half][3];
                float h0 = __bfloat162float(__float2bfloat16_rn(v0));
                float h1 = __bfloat162float(__float2bfloat16_rn(v1));
                float h2 = __bfloat162float(__float2bfloat16_rn(v2));
                float h3 = __bfloat162float(__float2bfloat16_rn(v3));
                pah[j][2*half + 0] = packbf2(h0, h1);
                pah[j][2*half + 1] = packbf2(h2, h3);
                pal[j][2*half + 0] = packbf2(v0 - h0, v1 - h1);
                pal[j][2*half + 1] = packbf2(v2 - h2, v3 - h3);
            }
        }

        #pragma unroll
        for (int j = 0; j < 2; j++) {
            #pragma unroll
            for (int nt2 = 0; nt2 < 8; nt2++) {
                int row = 16 * j + vrow;
                int col = 16 * nt2 + vsel;
                uint32_t r0, r1, r2, r3, u0, u1, u2, u3;
                ldsm4t(r0, r1, r2, r3, sptr(&sVh[row * KLD + col]));
                ldsm4t(u0, u1, u2, u3, sptr(&sVl[row * KLD + col]));
                mma_bf16(o[2*nt2],   pah[j], r0, r1);
                mma_bf16(o[2*nt2+1], pah[j], r2, r3);
                mma_bf16(o[2*nt2],   pah[j], u0, u1);
                mma_bf16(o[2*nt2+1], pah[j], u2, u3);
                mma_bf16(o[2*nt2],   pal[j], r0, r1);
                mma_bf16(o[2*nt2+1], pal[j], r2, r3);
            }
        }
    }

    float i0 = 1.0f / l0, i1 = 1.0f / l1;
    size_t base0 = (qrow0 + g) * EMBED + h * HDIM + 2 * t;
    size_t base1 = (qrow0 + g + 8) * EMBED + h * HDIM + 2 * t;
    #pragma unroll
    for (int nt = 0; nt < 16; nt++) {
        split_store2(o[nt][0] * i0, o[nt][1] * i0, &ctxh[base0 + 8 * nt], &ctxl[base0 + 8 * nt]);
        split_store2(o[nt][2] * i1, o[nt][3] * i1, &ctxh[base1 + 8 * nt], &ctxl[base1 + 8 * nt]);
    }
}

// ============================================================
// launcher
// ============================================================
extern "C" void kernel_launch(void* const* d_in, const int* in_sizes, int n_in,
                              void* d_out, int out_size)
{
    const float* query = (const float*)d_in[0];
    const float* key   = (const float*)d_in[1];
    const float* value = (const float*)d_in[2];
    const float* mask  = (const float*)d_in[3];
    const float* Wq    = (const float*)d_in[4];
    const float* Wk    = (const float*)d_in[5];
    const float* Wv    = (const float*)d_in[6];
    const float* Wo    = (const float*)d_in[7];
    float* out = (float*)d_out;

    bf16 *inh, *inl, *wh, *wl, *qh, *ql, *kh, *kl, *vh, *vl, *ctxh, *ctxl;
    cudaGetSymbolAddress((void**)&inh, g_inh);
    cudaGetSymbolAddress((void**)&inl, g_inl);
    cudaGetSymbolAddress((void**)&wh,  g_wh);
    cudaGetSymbolAddress((void**)&wl,  g_wl);
    cudaGetSymbolAddress((void**)&qh,  g_qh);
    cudaGetSymbolAddress((void**)&ql,  g_ql);
    cudaGetSymbolAddress((void**)&kh,  g_kh);
    cudaGetSymbolAddress((void**)&kl,  g_kl);
    cudaGetSymbolAddress((void**)&vh,  g_vh);
    cudaGetSymbolAddress((void**)&vl,  g_vl);
    cudaGetSymbolAddress((void**)&ctxh, g_ctxh);
    cudaGetSymbolAddress((void**)&ctxl, g_ctxl);

    cudaFuncSetAttribute(attn_mma, cudaFuncAttributeMaxDynamicSharedMemorySize, ATTN_SMEM);
    cudaFuncSetAttribute(gemm_proj, cudaFuncAttributeMaxDynamicSharedMemorySize, GEMM_SMEM);
    cudaFuncSetAttribute(gemm_out,  cudaFuncAttributeMaxDynamicSharedMemorySize, GEMM_SMEM);

    dim3 blk(256);

    // ---- fused split pass ----
    {
        SplitArgs a;
        a.src[0] = query; a.dh[0] = inh + 0 * (size_t)IN_STRIDE; a.dl[0] = inl + 0 * (size_t)IN_STRIDE;
        a.src[1] = key;   a.dh[1] = inh + 1 * (size_t)IN_STRIDE; a.dl[1] = inl + 1 * (size_t)IN_STRIDE;
        a.src[2] = value; a.dh[2] = inh + 2 * (size_t)IN_STRIDE; a.dl[2] = inl + 2 * (size_t)IN_STRIDE;
        a.src[3] = Wq;    a.dh[3] = wh + WQ_OFF;                 a.dl[3] = wl + WQ_OFF;
        a.src[4] = Wk;    a.dh[4] = wh + WK_OFF;                 a.dl[4] = wl + WK_OFF;
        a.src[5] = Wv;    a.dh[5] = wh + WV_OFF;                 a.dl[5] = wl + WV_OFF;
        a.src[6] = Wo;    a.dh[6] = wh + WO_OFF;                 a.dl[6] = wl + WO_OFF;
        fused_split<<<SPLIT_BLOCKS, blk>>>(a);
    }

    // ---- fused Q/K/V projections (1536 CTAs, 128 thr, 4 CTAs/SM) ----
    {
        ProjArgs p;
        p.Ah[0] = inh + 0 * (size_t)IN_STRIDE; p.Al[0] = inl + 0 * (size_t)IN_STRIDE;
        p.Ah[1] = inh + 1 * (size_t)IN_STRIDE; p.Al[1] = inl + 1 * (size_t)IN_STRIDE;
        p.Ah[2] = inh + 2 * (size_t)IN_STRIDE; p.Al[2] = inl + 2 * (size_t)IN_STRIDE;
        p.Bh[0] = wh + WQ_OFF; p.Bl[0] = wl + WQ_OFF;
        p.Bh[1] = wh + WK_OFF; p.Bl[1] = wl + WK_OFF;
        p.Bh[2] = wh + WV_OFF; p.Bl[2] = wl + WV_OFF;
        p.Ch[0] = qh; p.Cl[0] = ql;
        p.Ch[1] = kh; p.Cl[1] = kl;
        p.Ch[2] = vh; p.Cl[2] = vl;
        gemm_proj<<<1536, dim3(128), GEMM_SMEM>>>(p);
    }

    // ---- fused attention (4 warps/CTA, 2 CTAs/SM, 2-stage) ----
    attn_mma<<<dim3(SS / 64, NHEAD, BB), dim3(128), ATTN_SMEM>>>(
        qh, ql, kh, kl, vh, vl, mask, ctxh, ctxl);

    // ---- output projection (BM=64 tiles, 4 CTAs/SM) ----
    gemm_out<<<dim3(EMBED / 128, MROWS / 64), dim3(128), GEMM_SMEM>>>(
        ctxh, ctxl, wh + WO_OFF, wl + WO_OFF, out);
}